// round 1
// baseline (speedup 1.0000x reference)
#include <cuda_runtime.h>
#include <math.h>

// ----- problem constants -----
#define NODES   32768
#define NS      64      // scalar channels (0e in)
#define NV      32      // vector channels (1o in)
#define P0      64      // 0e out
#define Q1      32      // 1o out
#define R2      16      // 2e out
#define DIN     160
#define DOUT    240
#define NPAIR64 2080    // 64*65/2
#define NPAIR32 528     // 32*33/2

// ----- kernel tiling -----
#define NB      32      // nodes per CTA
#define THREADS 256
#define CHUNK   128     // pair-chunk for outer-product staging
#define VST     99      // padded row stride for vA (99 mod 32 = 3, coprime -> conflict-free)

// ----- preprocessed weights (device-global scratch; no allocation) -----
__device__ float d_g[NV];
__device__ float d_Wss [NPAIR64 * P0];        // [pair][p], c0*(W[u,v,p]+W[v,u,p]) (diag once)
__device__ float d_Wvv0[NPAIR32 * P0];        // [pair][p], (c0/sqrt3)*sym
__device__ float d_Wsv1[NS * NV * Q1];        // [u][v*32+q], c1-scaled
__device__ float d_Wvv2t[NV * NV * R2];       // [v][u*16+r], c2-scaled
__device__ unsigned short d_pairs64[NPAIR64]; // (u<<8)|v
__device__ unsigned short d_pairs32[NPAIR32];

// ================= prep kernels =================
__global__ void prep_g(const float* __restrict__ gates) {
    int i = threadIdx.x;
    if (i < NV) d_g[i] = tanhf(gates[i]);
}

__global__ void prep_ss(const float* __restrict__ W) {
    int idx = blockIdx.x * blockDim.x + threadIdx.x;
    if (idx >= 64 * 64 * 64) return;
    int p = idx & 63, v = (idx >> 6) & 63, u = idx >> 12;
    if (v < u) return;
    const float c0 = rsqrtf(5120.f);  // 1/sqrt(FAN0)
    float val = W[(u * 64 + v) * 64 + p];
    if (u != v) val += W[(v * 64 + u) * 64 + p];
    int k = u * 64 - (u * (u - 1)) / 2 + (v - u);
    d_Wss[k * 64 + p] = c0 * val;
    if (p == 0) d_pairs64[k] = (unsigned short)((u << 8) | v);
}

__global__ void prep_vv0(const float* __restrict__ W) {
    int idx = blockIdx.x * blockDim.x + threadIdx.x;
    if (idx >= 32 * 32 * 64) return;
    int p = idx & 63, v = (idx >> 6) & 31, u = idx >> 11;
    if (v < u) return;
    const float c = rsqrtf(5120.f) * rsqrtf(3.f);
    float val = W[(u * 32 + v) * 64 + p];
    if (u != v) val += W[(v * 32 + u) * 64 + p];
    int k = u * 32 - (u * (u - 1)) / 2 + (v - u);
    d_Wvv0[k * 64 + p] = c * val;
    if (p == 0) d_pairs32[k] = (unsigned short)((u << 8) | v);
}

__global__ void prep_sv1(const float* __restrict__ W) {
    int idx = blockIdx.x * blockDim.x + threadIdx.x;
    if (idx >= NS * NV * Q1) return;
    d_Wsv1[idx] = rsqrtf(2048.f) * W[idx];   // 1/sqrt(FAN1)
}

__global__ void prep_vv2(const float* __restrict__ W) {
    int idx = blockIdx.x * blockDim.x + threadIdx.x;
    if (idx >= NV * NV * R2) return;
    int r = idx & 15, v = (idx >> 4) & 31, u = idx >> 9;
    d_Wvv2t[v * (NV * R2) + u * R2 + r] = 0.03125f * W[(u * 32 + v) * 16 + r]; // c2 = 1/32
}

// ================= main kernel =================
__global__ __launch_bounds__(THREADS) void nltsq_main(
    const float* __restrict__ feats, float* __restrict__ out)
{
    __shared__ __align__(16) float sT[NS * NB];     // [u][n]  (node-minor for float4 loads)
    __shared__ __align__(16) float vA[NB * VST];    // [n][vec*3+i], padded stride
    __shared__ __align__(16) float xs[CHUNK * NB];  // outer-product / dot feature tile
    __shared__ float gs[NV];

    const int tid = threadIdx.x;
    const int nodeBase = blockIdx.x * NB;

    if (tid < NV) gs[tid] = d_g[tid];
    __syncthreads();

    // ---- Phase A: load + activate ----
    for (int idx = tid; idx < NB * DIN; idx += THREADS) {
        int n = idx / DIN, c = idx % DIN;
        float f = feats[(size_t)(nodeBase + n) * DIN + c];
        if (c < NS) {
            sT[c * NB + n] = tanhf(f);
        } else {
            int j = c - NS;
            vA[n * VST + j] = f * gs[j / 3];
        }
    }
    __syncthreads();

    // ---- Phase B: out0 (ss pairs + vv dot-pairs), 64 p outputs ----
    float acc0[8];
    #pragma unroll
    for (int i = 0; i < 8; i++) acc0[i] = 0.f;
    const int px  = tid & 63;     // p index (warp lanes contiguous -> coalesced W)
    const int grp = tid >> 6;     // 0..3, nodes grp*8 .. grp*8+7

    // --- ss pairs ---
    for (int base = 0; base < NPAIR64; base += CHUNK) {
        int csize = min(CHUNK, NPAIR64 - base);
        for (int idx = tid; idx < csize * NB; idx += THREADS) {
            int pl = idx >> 5, n = idx & 31;
            unsigned int pr = d_pairs64[base + pl];
            int u = pr >> 8, v = pr & 255;
            xs[pl * NB + n] = sT[u * NB + n] * sT[v * NB + n];
        }
        __syncthreads();
        const float* wp = d_Wss + (size_t)base * P0 + px;
        const float4* xs4 = (const float4*)xs;
        #pragma unroll 2
        for (int k = 0; k < csize; k++) {
            float  w  = wp[k * P0];
            float4 xa = xs4[k * 8 + grp * 2];
            float4 xb = xs4[k * 8 + grp * 2 + 1];
            acc0[0] += w * xa.x; acc0[1] += w * xa.y;
            acc0[2] += w * xa.z; acc0[3] += w * xa.w;
            acc0[4] += w * xb.x; acc0[5] += w * xb.y;
            acc0[6] += w * xb.z; acc0[7] += w * xb.w;
        }
        __syncthreads();
    }

    // --- vv dot-pairs ---
    for (int base = 0; base < NPAIR32; base += CHUNK) {
        int csize = min(CHUNK, NPAIR32 - base);
        for (int idx = tid; idx < csize * NB; idx += THREADS) {
            int pl = idx >> 5, n = idx & 31;
            unsigned int pr = d_pairs32[base + pl];
            int u = pr >> 8, v = pr & 255;
            const float* vr = vA + n * VST;
            xs[pl * NB + n] = vr[u * 3 + 0] * vr[v * 3 + 0]
                            + vr[u * 3 + 1] * vr[v * 3 + 1]
                            + vr[u * 3 + 2] * vr[v * 3 + 2];
        }
        __syncthreads();
        const float* wp = d_Wvv0 + (size_t)base * P0 + px;
        const float4* xs4 = (const float4*)xs;
        #pragma unroll 2
        for (int k = 0; k < csize; k++) {
            float  w  = wp[k * P0];
            float4 xa = xs4[k * 8 + grp * 2];
            float4 xb = xs4[k * 8 + grp * 2 + 1];
            acc0[0] += w * xa.x; acc0[1] += w * xa.y;
            acc0[2] += w * xa.z; acc0[3] += w * xa.w;
            acc0[4] += w * xb.x; acc0[5] += w * xb.y;
            acc0[6] += w * xb.z; acc0[7] += w * xb.w;
        }
        __syncthreads();
    }

    #pragma unroll
    for (int i = 0; i < 8; i++) {
        int n = grp * 8 + i;
        out[(size_t)(nodeBase + n) * DOUT + px] = acc0[i];
    }

    // ---- Phase C: out1 via T[v,q] = sum_u s_u W_sv1 ----
    {
        const int q  = tid & 31;
        const int g4 = tid >> 5;          // 0..7 -> nodes g4*4 .. g4*4+3
        float a1[12];
        #pragma unroll
        for (int i = 0; i < 12; i++) a1[i] = 0.f;

        for (int v = 0; v < NV; v++) {
            float t0 = 0.f, t1 = 0.f, t2 = 0.f, t3 = 0.f;
            const float* wp = d_Wsv1 + v * 32 + q;
            #pragma unroll 4
            for (int u = 0; u < NS; u++) {
                float  w  = wp[u * (NV * Q1)];
                float4 s4 = *(const float4*)&sT[u * NB + g4 * 4];
                t0 += w * s4.x; t1 += w * s4.y; t2 += w * s4.z; t3 += w * s4.w;
            }
            #pragma unroll
            for (int jj = 0; jj < 4; jj++) {
                int n = g4 * 4 + jj;
                float tt = (jj == 0) ? t0 : (jj == 1) ? t1 : (jj == 2) ? t2 : t3;
                const float* vr = vA + n * VST + v * 3;
                a1[jj * 3 + 0] += tt * vr[0];
                a1[jj * 3 + 1] += tt * vr[1];
                a1[jj * 3 + 2] += tt * vr[2];
            }
        }
        #pragma unroll
        for (int jj = 0; jj < 4; jj++) {
            int n = g4 * 4 + jj;
            float* o = out + (size_t)(nodeBase + n) * DOUT + NS + q * 3;
            o[0] = a1[jj * 3 + 0]; o[1] = a1[jj * 3 + 1]; o[2] = a1[jj * 3 + 2];
        }
    }

    // ---- Phase D: out2 via tv[u,j,r] factorization ----
    {
        const int r   = tid & 15;
        const int g16 = tid >> 4;         // 0..15 -> nodes g16*2, g16*2+1
        for (int nn = 0; nn < 2; nn++) {
            int n = g16 * 2 + nn;
            float S[9];
            #pragma unroll
            for (int i = 0; i < 9; i++) S[i] = 0.f;
            const float* vrow = vA + n * VST;

            for (int u = 0; u < NV; u++) {
                float t0 = 0.f, t1 = 0.f, t2 = 0.f;
                const float* wp = d_Wvv2t + u * R2 + r;
                #pragma unroll 4
                for (int v = 0; v < NV; v++) {
                    float w = wp[v * (NV * R2)];
                    t0 += w * vrow[v * 3 + 0];
                    t1 += w * vrow[v * 3 + 1];
                    t2 += w * vrow[v * 3 + 2];
                }
                float vu0 = vrow[u * 3 + 0], vu1 = vrow[u * 3 + 1], vu2 = vrow[u * 3 + 2];
                S[0] += vu0 * t0; S[1] += vu0 * t1; S[2] += vu0 * t2;
                S[3] += vu1 * t0; S[4] += vu1 * t1; S[5] += vu1 * t2;
                S[6] += vu2 * t0; S[7] += vu2 * t1; S[8] += vu2 * t2;
            }
            const float is2 = 0.70710678118654752f;   // 1/sqrt(2)
            const float is6 = 0.40824829046386302f;   // 1/sqrt(6)
            float* o = out + (size_t)(nodeBase + n) * DOUT + (NS + 3 * Q1) + r * 5;
            o[0] = (S[1] + S[3]) * is2;
            o[1] = (S[5] + S[7]) * is2;
            o[2] = (2.f * S[8] - S[0] - S[4]) * is6;
            o[3] = (S[2] + S[6]) * is2;
            o[4] = (S[0] - S[4]) * is2;
        }
    }
}

// ================= launch =================
extern "C" void kernel_launch(void* const* d_in, const int* in_sizes, int n_in,
                              void* d_out, int out_size)
{
    const float* feats = (const float*)d_in[0];
    const float* gates = (const float*)d_in[1];
    const float* Wss0  = (const float*)d_in[2];
    const float* Wsv1  = (const float*)d_in[3];
    const float* Wvv0  = (const float*)d_in[4];
    const float* Wvv2  = (const float*)d_in[5];
    float* out = (float*)d_out;

    prep_g  <<<1, 32>>>(gates);
    prep_ss <<<(64 * 64 * 64 + 255) / 256, 256>>>(Wss0);
    prep_vv0<<<(32 * 32 * 64 + 255) / 256, 256>>>(Wvv0);
    prep_sv1<<<(NS * NV * Q1 + 255) / 256, 256>>>(Wsv1);
    prep_vv2<<<(NV * NV * R2 + 255) / 256, 256>>>(Wvv2);

    nltsq_main<<<NODES / NB, THREADS>>>(feats, out);
}

// round 2
// speedup vs baseline: 1.0017x; 1.0017x over previous
#include <cuda_runtime.h>
#include <math.h>

// ----- problem constants -----
#define NODES   32768
#define NS      64      // scalar channels (0e in)
#define NV      32      // vector channels (1o in)
#define P0      64      // 0e out
#define Q1      32      // 1o out
#define R2      16      // 2e out
#define DIN     160
#define DOUT    240
#define NPAIR64 2080    // 64*65/2
#define NPAIR32 528     // 32*33/2

// ----- kernel tiling -----
#define NB      32      // nodes per CTA
#define THREADS 256
#define CHUNK   128     // pair-chunk for outer-product staging
#define VST     99      // padded row stride for vA (99 mod 32 = 3, coprime -> conflict-free)

// ----- preprocessed weights (device-global scratch; no allocation) -----
__device__ float d_g[NV];
__device__ float d_Wss [NPAIR64 * P0];        // [pair][p], c0*(W[u,v,p]+W[v,u,p]) (diag once)
__device__ float d_Wvv0[NPAIR32 * P0];        // [pair][p], (c0/sqrt3)*sym
__device__ float d_Wsv1[NS * NV * Q1];        // [u][v*32+q], c1-scaled
__device__ float d_Wvv2t[NV * NV * R2];       // [v][u*16+r], c2-scaled
__device__ unsigned short d_pairs64[NPAIR64]; // (u<<8)|v
__device__ unsigned short d_pairs32[NPAIR32];

// ================= prep kernels =================
__global__ void prep_g(const float* __restrict__ gates) {
    int i = threadIdx.x;
    if (i < NV) d_g[i] = tanhf(gates[i]);
}

__global__ void prep_ss(const float* __restrict__ W) {
    int idx = blockIdx.x * blockDim.x + threadIdx.x;
    if (idx >= 64 * 64 * 64) return;
    int p = idx & 63, v = (idx >> 6) & 63, u = idx >> 12;
    if (v < u) return;
    const float c0 = rsqrtf(5120.f);  // 1/sqrt(FAN0)
    float val = W[(u * 64 + v) * 64 + p];
    if (u != v) val += W[(v * 64 + u) * 64 + p];
    int k = u * 64 - (u * (u - 1)) / 2 + (v - u);
    d_Wss[k * 64 + p] = c0 * val;
    if (p == 0) d_pairs64[k] = (unsigned short)((u << 8) | v);
}

__global__ void prep_vv0(const float* __restrict__ W) {
    int idx = blockIdx.x * blockDim.x + threadIdx.x;
    if (idx >= 32 * 32 * 64) return;
    int p = idx & 63, v = (idx >> 6) & 31, u = idx >> 11;
    if (v < u) return;
    const float c = rsqrtf(5120.f) * rsqrtf(3.f);
    float val = W[(u * 32 + v) * 64 + p];
    if (u != v) val += W[(v * 32 + u) * 64 + p];
    int k = u * 32 - (u * (u - 1)) / 2 + (v - u);
    d_Wvv0[k * 64 + p] = c * val;
    if (p == 0) d_pairs32[k] = (unsigned short)((u << 8) | v);
}

__global__ void prep_sv1(const float* __restrict__ W) {
    int idx = blockIdx.x * blockDim.x + threadIdx.x;
    if (idx >= NS * NV * Q1) return;
    d_Wsv1[idx] = rsqrtf(2048.f) * W[idx];   // 1/sqrt(FAN1)
}

__global__ void prep_vv2(const float* __restrict__ W) {
    int idx = blockIdx.x * blockDim.x + threadIdx.x;
    if (idx >= NV * NV * R2) return;
    int r = idx & 15, v = (idx >> 4) & 31, u = idx >> 9;
    d_Wvv2t[v * (NV * R2) + u * R2 + r] = 0.03125f * W[(u * 32 + v) * 16 + r]; // c2 = 1/32
}

// ================= main kernel =================
__global__ __launch_bounds__(THREADS) void nltsq_main(
    const float* __restrict__ feats, float* __restrict__ out)
{
    __shared__ __align__(16) float sT[NS * NB];     // [u][n]  (node-minor for float4 loads)
    __shared__ __align__(16) float vA[NB * VST];    // [n][vec*3+i], padded stride
    __shared__ __align__(16) float xs[CHUNK * NB];  // outer-product / dot feature tile
    __shared__ float gs[NV];

    const int tid = threadIdx.x;
    const int nodeBase = blockIdx.x * NB;

    if (tid < NV) gs[tid] = d_g[tid];
    __syncthreads();

    // ---- Phase A: load + activate ----
    for (int idx = tid; idx < NB * DIN; idx += THREADS) {
        int n = idx / DIN, c = idx % DIN;
        float f = feats[(size_t)(nodeBase + n) * DIN + c];
        if (c < NS) {
            sT[c * NB + n] = tanhf(f);
        } else {
            int j = c - NS;
            vA[n * VST + j] = f * gs[j / 3];
        }
    }
    __syncthreads();

    // ---- Phase B: out0 (ss pairs + vv dot-pairs), 64 p outputs ----
    float acc0[8];
    #pragma unroll
    for (int i = 0; i < 8; i++) acc0[i] = 0.f;
    const int px  = tid & 63;     // p index (warp lanes contiguous -> coalesced W)
    const int grp = tid >> 6;     // 0..3, nodes grp*8 .. grp*8+7

    // --- ss pairs ---
    for (int base = 0; base < NPAIR64; base += CHUNK) {
        int csize = min(CHUNK, NPAIR64 - base);
        for (int idx = tid; idx < csize * NB; idx += THREADS) {
            int pl = idx >> 5, n = idx & 31;
            unsigned int pr = d_pairs64[base + pl];
            int u = pr >> 8, v = pr & 255;
            xs[pl * NB + n] = sT[u * NB + n] * sT[v * NB + n];
        }
        __syncthreads();
        const float* wp = d_Wss + (size_t)base * P0 + px;
        const float4* xs4 = (const float4*)xs;
        #pragma unroll 2
        for (int k = 0; k < csize; k++) {
            float  w  = wp[k * P0];
            float4 xa = xs4[k * 8 + grp * 2];
            float4 xb = xs4[k * 8 + grp * 2 + 1];
            acc0[0] += w * xa.x; acc0[1] += w * xa.y;
            acc0[2] += w * xa.z; acc0[3] += w * xa.w;
            acc0[4] += w * xb.x; acc0[5] += w * xb.y;
            acc0[6] += w * xb.z; acc0[7] += w * xb.w;
        }
        __syncthreads();
    }

    // --- vv dot-pairs ---
    for (int base = 0; base < NPAIR32; base += CHUNK) {
        int csize = min(CHUNK, NPAIR32 - base);
        for (int idx = tid; idx < csize * NB; idx += THREADS) {
            int pl = idx >> 5, n = idx & 31;
            unsigned int pr = d_pairs32[base + pl];
            int u = pr >> 8, v = pr & 255;
            const float* vr = vA + n * VST;
            xs[pl * NB + n] = vr[u * 3 + 0] * vr[v * 3 + 0]
                            + vr[u * 3 + 1] * vr[v * 3 + 1]
                            + vr[u * 3 + 2] * vr[v * 3 + 2];
        }
        __syncthreads();
        const float* wp = d_Wvv0 + (size_t)base * P0 + px;
        const float4* xs4 = (const float4*)xs;
        #pragma unroll 2
        for (int k = 0; k < csize; k++) {
            float  w  = wp[k * P0];
            float4 xa = xs4[k * 8 + grp * 2];
            float4 xb = xs4[k * 8 + grp * 2 + 1];
            acc0[0] += w * xa.x; acc0[1] += w * xa.y;
            acc0[2] += w * xa.z; acc0[3] += w * xa.w;
            acc0[4] += w * xb.x; acc0[5] += w * xb.y;
            acc0[6] += w * xb.z; acc0[7] += w * xb.w;
        }
        __syncthreads();
    }

    #pragma unroll
    for (int i = 0; i < 8; i++) {
        int n = grp * 8 + i;
        out[(size_t)(nodeBase + n) * DOUT + px] = acc0[i];
    }

    // ---- Phase C: out1 via T[v,q] = sum_u s_u W_sv1 ----
    {
        const int q  = tid & 31;
        const int g4 = tid >> 5;          // 0..7 -> nodes g4*4 .. g4*4+3
        float a1[12];
        #pragma unroll
        for (int i = 0; i < 12; i++) a1[i] = 0.f;

        for (int v = 0; v < NV; v++) {
            float t0 = 0.f, t1 = 0.f, t2 = 0.f, t3 = 0.f;
            const float* wp = d_Wsv1 + v * 32 + q;
            #pragma unroll 4
            for (int u = 0; u < NS; u++) {
                float  w  = wp[u * (NV * Q1)];
                float4 s4 = *(const float4*)&sT[u * NB + g4 * 4];
                t0 += w * s4.x; t1 += w * s4.y; t2 += w * s4.z; t3 += w * s4.w;
            }
            #pragma unroll
            for (int jj = 0; jj < 4; jj++) {
                int n = g4 * 4 + jj;
                float tt = (jj == 0) ? t0 : (jj == 1) ? t1 : (jj == 2) ? t2 : t3;
                const float* vr = vA + n * VST + v * 3;
                a1[jj * 3 + 0] += tt * vr[0];
                a1[jj * 3 + 1] += tt * vr[1];
                a1[jj * 3 + 2] += tt * vr[2];
            }
        }
        #pragma unroll
        for (int jj = 0; jj < 4; jj++) {
            int n = g4 * 4 + jj;
            float* o = out + (size_t)(nodeBase + n) * DOUT + NS + q * 3;
            o[0] = a1[jj * 3 + 0]; o[1] = a1[jj * 3 + 1]; o[2] = a1[jj * 3 + 2];
        }
    }

    // ---- Phase D: out2 via tv[u,j,r] factorization ----
    {
        const int r   = tid & 15;
        const int g16 = tid >> 4;         // 0..15 -> nodes g16*2, g16*2+1
        for (int nn = 0; nn < 2; nn++) {
            int n = g16 * 2 + nn;
            float S[9];
            #pragma unroll
            for (int i = 0; i < 9; i++) S[i] = 0.f;
            const float* vrow = vA + n * VST;

            for (int u = 0; u < NV; u++) {
                float t0 = 0.f, t1 = 0.f, t2 = 0.f;
                const float* wp = d_Wvv2t + u * R2 + r;
                #pragma unroll 4
                for (int v = 0; v < NV; v++) {
                    float w = wp[v * (NV * R2)];
                    t0 += w * vrow[v * 3 + 0];
                    t1 += w * vrow[v * 3 + 1];
                    t2 += w * vrow[v * 3 + 2];
                }
                float vu0 = vrow[u * 3 + 0], vu1 = vrow[u * 3 + 1], vu2 = vrow[u * 3 + 2];
                S[0] += vu0 * t0; S[1] += vu0 * t1; S[2] += vu0 * t2;
                S[3] += vu1 * t0; S[4] += vu1 * t1; S[5] += vu1 * t2;
                S[6] += vu2 * t0; S[7] += vu2 * t1; S[8] += vu2 * t2;
            }
            const float is2 = 0.70710678118654752f;   // 1/sqrt(2)
            const float is6 = 0.40824829046386302f;   // 1/sqrt(6)
            float* o = out + (size_t)(nodeBase + n) * DOUT + (NS + 3 * Q1) + r * 5;
            o[0] = (S[1] + S[3]) * is2;
            o[1] = (S[5] + S[7]) * is2;
            o[2] = (2.f * S[8] - S[0] - S[4]) * is6;
            o[3] = (S[2] + S[6]) * is2;
            o[4] = (S[0] - S[4]) * is2;
        }
    }
}

// ================= launch =================
extern "C" void kernel_launch(void* const* d_in, const int* in_sizes, int n_in,
                              void* d_out, int out_size)
{
    const float* feats = (const float*)d_in[0];
    const float* gates = (const float*)d_in[1];
    const float* Wss0  = (const float*)d_in[2];
    const float* Wsv1  = (const float*)d_in[3];
    const float* Wvv0  = (const float*)d_in[4];
    const float* Wvv2  = (const float*)d_in[5];
    float* out = (float*)d_out;

    prep_g  <<<1, 32>>>(gates);
    prep_ss <<<(64 * 64 * 64 + 255) / 256, 256>>>(Wss0);
    prep_vv0<<<(32 * 32 * 64 + 255) / 256, 256>>>(Wvv0);
    prep_sv1<<<(NS * NV * Q1 + 255) / 256, 256>>>(Wsv1);
    prep_vv2<<<(NV * NV * R2 + 255) / 256, 256>>>(Wvv2);

    nltsq_main<<<NODES / NB, THREADS>>>(feats, out);
}

// round 4
// speedup vs baseline: 2.3791x; 2.3751x over previous
#include <cuda_runtime.h>
#include <cuda_fp16.h>
#include <mma.h>
#include <math.h>
#include <stdint.h>

using namespace nvcuda;

// ================= problem constants =================
#define NODES   32768
#define CTA_M   128
#define THREADS 256
#define DOUT    240
#define KTOT    2624            // 2080 ss + 528 vv + 16 pad = 41*64
#define KCH0    41
#define NPAIR2  528             // 32*33/2
#define PGRPS   33              // 528/16 pair-groups for out2

// ================= smem layout (bytes) =================
#define VF_LD    97
#define SH_LD    72
#define XB_LD    88
#define YS_LD    136
#define OFF_VF   0                          // float vF[128][97]   49664
#define OFF_SH   49664                      // half  sH[128][72]   18432
#define OFF_XB   68096                      // half  XB[128][88]   22528
#define OFF_YS   90624                      // float YS col-major  69632 (ld 136, <=128 cols)
#define SMEM_TOTAL 160256

// ================= preprocessed weights (gmem) =================
__device__ __half d_Wcat[KTOT * 64];        // [k][p]
__device__ __half d_Wc1 [64 * 1024];        // [u][q*32+v]
__device__ __half d_Wc2 [PGRPS * 80 * 16];  // [(pg*80 + m*16 + pi)][r]
__device__ unsigned short d_pairs [KTOT];   // (u<<8)|v  for GEMM0
__device__ unsigned short d_pairs2[NPAIR2]; // (u<<8)|v  for out2 pairs
__device__ float d_g[32];

#define B_CAT 0
#define N_CAT (KTOT * 64)                   // 167936
#define B_C1  N_CAT                         // 167936
#define N_C1  (64 * 1024)                   // 65536
#define B_C2  (B_C1 + N_C1)                 // 233472
#define N_C2  (PGRPS * 80 * 16)             // 42240
#define B_PR  (B_C2 + N_C2)                 // 275712
#define B_PR2 (B_PR + KTOT)                 // 278336
#define B_G   (B_PR2 + NPAIR2)              // 278864
#define N_ALL (B_G + 32)                    // 278896

// ================= prep kernel =================
__device__ __forceinline__ void pair_decode(int k, int width, int& u, int& v) {
    int uu = 0, rem = k;
    while (rem >= width - uu) { rem -= width - uu; uu++; }
    u = uu; v = uu + rem;
}

__global__ void prep_all(const float* __restrict__ gates, const float* __restrict__ Wss0,
                         const float* __restrict__ Wsv1, const float* __restrict__ Wvv0,
                         const float* __restrict__ Wvv2) {
    int idx = blockIdx.x * blockDim.x + threadIdx.x;
    if (idx >= N_ALL) return;
    const float c0  = rsqrtf(5120.f);
    const float cvv = c0 * rsqrtf(3.f);
    const float c1  = rsqrtf(2048.f);
    const float c2  = 0.03125f;
    const float is2 = 0.70710678118654752f;
    const float is6 = 0.40824829046386302f;

    if (idx < N_CAT) {
        int k = idx >> 6, p = idx & 63;
        float val = 0.f;
        if (k < 2080) {
            int u, v; pair_decode(k, 64, u, v);
            val = c0 * Wss0[(u * 64 + v) * 64 + p];
            if (u != v) val += c0 * Wss0[(v * 64 + u) * 64 + p];
        } else if (k < 2608) {
            int u, v; pair_decode(k - 2080, 32, u, v);
            val = cvv * Wvv0[(u * 32 + v) * 64 + p];
            if (u != v) val += cvv * Wvv0[(v * 32 + u) * 64 + p];
        }
        d_Wcat[idx] = __float2half_rn(val);
    } else if (idx < B_C2) {
        int o = idx - B_C1;
        int u = o >> 10, n = o & 1023;
        int q = n >> 5, v = n & 31;
        d_Wc1[o] = __float2half_rn(c1 * Wsv1[u * 1024 + v * 32 + q]);
    } else if (idx < B_PR) {
        int o = idx - B_C2;
        int k2 = o >> 4, r = o & 15;
        int pg = k2 / 80, rem = k2 % 80;
        int m = rem >> 4, pi = rem & 15;
        int pair = pg * 16 + pi;
        int u, v; pair_decode(pair, 32, u, v);
        float w = Wvv2[(u * 32 + v) * 16 + r];
        if (u != v) w += Wvv2[(v * 32 + u) * 16 + r];
        float sc = (m == 2) ? is6 : is2;
        d_Wc2[o] = __float2half_rn(c2 * sc * w);
    } else if (idx < B_PR2) {
        int k = idx - B_PR;
        unsigned short pr = 0;
        if (k < 2080)      { int u, v; pair_decode(k, 64, u, v);        pr = (unsigned short)((u << 8) | v); }
        else if (k < 2608) { int u, v; pair_decode(k - 2080, 32, u, v); pr = (unsigned short)((u << 8) | v); }
        else pr = 0xFFFF;
        d_pairs[k] = pr;
    } else if (idx < B_G) {
        int k = idx - B_PR2;
        int u, v; pair_decode(k, 32, u, v);
        d_pairs2[k] = (unsigned short)((u << 8) | v);
    } else {
        int i = idx - B_G;
        d_g[i] = tanhf(gates[i]);
    }
}

// ================= main kernel =================
__global__ __launch_bounds__(THREADS, 1) void nltsq_main(
    const float* __restrict__ feats, float* __restrict__ out) {
    extern __shared__ char smem[];
    float*  vF = (float*)(smem + OFF_VF);
    __half* sH = (__half*)(smem + OFF_SH);
    __half* XB = (__half*)(smem + OFF_XB);
    float*  YS = (float*)(smem + OFF_YS);

    const int tid  = threadIdx.x;
    const int wid  = tid >> 5;
    const int wrow = wid * 16;                 // this warp's M strip
    const int nodeBase = blockIdx.x * CTA_M;

    // ---- Phase A: load + activate ----
    for (int idx = tid; idx < CTA_M * 160; idx += THREADS) {
        int n = idx / 160, c = idx % 160;
        float f = feats[(size_t)(nodeBase + n) * 160 + c];
        if (c < 64) {
            sH[n * SH_LD + c] = __float2half_rn(tanhf(f));
        } else {
            int j = c - 64;
            vF[n * VF_LD + j] = f * d_g[j / 3];
        }
    }
    __syncthreads();

    // ======== GEMM 0: out0[128x64] = X[128x2624] @ Wcat ========
    {
        wmma::fragment<wmma::accumulator, 16, 16, 16, float> acc[4];
        #pragma unroll
        for (int nt = 0; nt < 4; nt++) wmma::fill_fragment(acc[nt], 0.f);

        const int kk = tid & 63, mg = tid >> 6;      // col, row-group of 32
        for (int kc = 0; kc < KCH0; kc++) {
            int kglob = kc * 64 + kk;
            unsigned int pr = d_pairs[kglob];
            int u = pr >> 8, v = pr & 255;
            if (kglob < 2080) {
                #pragma unroll 8
                for (int mi = 0; mi < 32; mi++) {
                    int m = mg * 32 + mi;
                    XB[m * XB_LD + kk] = __hmul(sH[m * SH_LD + u], sH[m * SH_LD + v]);
                }
            } else if (kglob < 2608) {
                #pragma unroll 4
                for (int mi = 0; mi < 32; mi++) {
                    int m = mg * 32 + mi;
                    const float* vr = vF + m * VF_LD;
                    float x = vr[u * 3] * vr[v * 3] + vr[u * 3 + 1] * vr[v * 3 + 1]
                            + vr[u * 3 + 2] * vr[v * 3 + 2];
                    XB[m * XB_LD + kk] = __float2half_rn(x);
                }
            } else {
                #pragma unroll 8
                for (int mi = 0; mi < 32; mi++)
                    XB[(mg * 32 + mi) * XB_LD + kk] = __half(0.f);
            }
            __syncthreads();
            #pragma unroll
            for (int ks = 0; ks < 4; ks++) {
                wmma::fragment<wmma::matrix_a, 16, 16, 16, __half, wmma::row_major> a;
                wmma::load_matrix_sync(a, XB + wrow * XB_LD + ks * 16, XB_LD);
                #pragma unroll
                for (int nt = 0; nt < 4; nt++) {
                    wmma::fragment<wmma::matrix_b, 16, 16, 16, __half, wmma::row_major> b;
                    wmma::load_matrix_sync(b, d_Wcat + (kc * 64 + ks * 16) * 64 + nt * 16, 64);
                    wmma::mma_sync(acc[nt], a, b, acc[nt]);
                }
            }
            __syncthreads();
        }
        #pragma unroll
        for (int nt = 0; nt < 4; nt++)
            wmma::store_matrix_sync(out + (size_t)(nodeBase + wrow) * DOUT + nt * 16,
                                    acc[nt], DOUT, wmma::mem_row_major);
    }

    // ======== GEMM 1: Y[128x1024] = sH @ Wc1; out1 = Y . v ========
    {
        wmma::fragment<wmma::matrix_a, 16, 16, 16, __half, wmma::row_major> a1[4];
        #pragma unroll
        for (int ks = 0; ks < 4; ks++)
            wmma::load_matrix_sync(a1[ks], sH + wrow * SH_LD + ks * 16, SH_LD);

        const int n  = tid >> 1;         // epilogue node
        const int qh = tid & 1;          // which half of the 4 q's
        float* orow = out + (size_t)(nodeBase + n) * DOUT;

        for (int nc = 0; nc < 8; nc++) {
            __syncthreads();             // prior epilogue done with YS
            #pragma unroll
            for (int nt = 0; nt < 8; nt++) {
                wmma::fragment<wmma::accumulator, 16, 16, 16, float> acc;
                wmma::fill_fragment(acc, 0.f);
                #pragma unroll
                for (int ks = 0; ks < 4; ks++) {
                    wmma::fragment<wmma::matrix_b, 16, 16, 16, __half, wmma::row_major> b;
                    wmma::load_matrix_sync(b, d_Wc1 + (ks * 16) * 1024 + nc * 128 + nt * 16, 1024);
                    wmma::mma_sync(acc, a1[ks], b, acc);
                }
                // stage col-major: elem(i=node, j=col) at YS[i + j*YS_LD]
                wmma::store_matrix_sync(YS + wrow + (nt * 16) * YS_LD, acc, YS_LD,
                                        wmma::mem_col_major);
            }
            __syncthreads();
            // epilogue: 4 q's in this chunk
            #pragma unroll
            for (int qq = 0; qq < 2; qq++) {
                int lq = qh * 2 + qq;            // 0..3
                int q  = nc * 4 + lq;
                const float* ycol = YS + n + (lq * 32) * YS_LD;
                const float* vr   = vF + n * VF_LD;
                float a0 = 0.f, a1s = 0.f, a2 = 0.f;
                #pragma unroll
                for (int v = 0; v < 32; v++) {
                    float y = ycol[v * YS_LD];
                    a0  += y * vr[v * 3];
                    a1s += y * vr[v * 3 + 1];
                    a2  += y * vr[v * 3 + 2];
                }
                orow[64 + q * 3]     = a0;
                orow[64 + q * 3 + 1] = a1s;
                orow[64 + q * 3 + 2] = a2;
            }
        }
    }

    // ======== GEMM 2: out2 via symmetric pair features ========
    {
        wmma::fragment<wmma::accumulator, 16, 16, 16, float> acc2[5];
        #pragma unroll
        for (int m = 0; m < 5; m++) wmma::fill_fragment(acc2[m], 0.f);

        const int pi = tid & 15, rg = tid >> 4;   // pair-in-group, row-group of 8
        for (int pg = 0; pg < PGRPS; pg++) {
            __syncthreads();                      // mma of prev chunk done with XB
            unsigned int pr = d_pairs2[pg * 16 + pi];
            int u = pr >> 8, v = pr & 255;
            #pragma unroll
            for (int mi = 0; mi < 8; mi++) {
                int mrow = rg * 8 + mi;
                const float* vr = vF + mrow * VF_LD;
                float u0 = vr[u * 3], u1 = vr[u * 3 + 1], u2 = vr[u * 3 + 2];
                float w0 = vr[v * 3], w1 = vr[v * 3 + 1], w2 = vr[v * 3 + 2];
                float aa = u0 * w0, bb = u1 * w1;
                __half* xr = XB + mrow * XB_LD + pi;
                xr[0]  = __float2half_rn(u0 * w1 + u1 * w0);           // m=0
                xr[16] = __float2half_rn(u1 * w2 + u2 * w1);           // m=1
                xr[32] = __float2half_rn(2.f * u2 * w2 - aa - bb);     // m=2
                xr[48] = __float2half_rn(u0 * w2 + u2 * w0);           // m=3
                xr[64] = __float2half_rn(aa - bb);                     // m=4
            }
            __syncthreads();
            #pragma unroll
            for (int m = 0; m < 5; m++) {
                wmma::fragment<wmma::matrix_a, 16, 16, 16, __half, wmma::row_major> a;
                wmma::fragment<wmma::matrix_b, 16, 16, 16, __half, wmma::row_major> b;
                wmma::load_matrix_sync(a, XB + wrow * XB_LD + m * 16, XB_LD);
                wmma::load_matrix_sync(b, d_Wc2 + (pg * 80 + m * 16) * 16, 16);
                wmma::mma_sync(acc2[m], a, b, acc2[m]);
            }
        }
        __syncthreads();                          // YS free (epilogue of GEMM1 done)
        #pragma unroll
        for (int m = 0; m < 5; m++)
            wmma::store_matrix_sync(YS + wrow + (m * 16) * YS_LD, acc2[m], YS_LD,
                                    wmma::mem_col_major);
        __syncthreads();
        for (int idx = tid; idx < CTA_M * 80; idx += THREADS) {
            int n = idx / 80, c = idx % 80;
            int m = c >> 4, r = c & 15;
            out[(size_t)(nodeBase + n) * DOUT + 160 + r * 5 + m] = YS[n + c * YS_LD];
        }
    }
}

// ================= launch =================
extern "C" void kernel_launch(void* const* d_in, const int* in_sizes, int n_in,
                              void* d_out, int out_size) {
    const float* feats = (const float*)d_in[0];
    const float* gates = (const float*)d_in[1];
    const float* Wss0  = (const float*)d_in[2];
    const float* Wsv1  = (const float*)d_in[3];
    const float* Wvv0  = (const float*)d_in[4];
    const float* Wvv2  = (const float*)d_in[5];
    float* out = (float*)d_out;

    static bool attr_set = false;
    if (!attr_set) {
        cudaFuncSetAttribute(nltsq_main, cudaFuncAttributeMaxDynamicSharedMemorySize, SMEM_TOTAL);
        attr_set = true;
    }

    prep_all<<<(N_ALL + 255) / 256, 256>>>(gates, Wss0, Wsv1, Wvv0, Wvv2);
    nltsq_main<<<NODES / CTA_M, THREADS, SMEM_TOTAL>>>(feats, out);
}

// round 5
// speedup vs baseline: 5.2790x; 2.2189x over previous
#include <cuda_runtime.h>
#include <cuda_fp16.h>
#include <mma.h>
#include <math.h>
#include <stdint.h>

using namespace nvcuda;

// ================= problem constants =================
#define NODES   32768
#define CTA_M   128
#define THREADS 256
#define DOUT    240
#define KTOT    2624            // 2080 ss + 528 vv + 16 pad = 41*64
#define KCH0    41
#define NPAIR2  528
#define PGRPS   33              // 528/16

// ================= smem layout =================
#define LD       136            // halves; multiple of 8 for wmma
#define WB_LD    72             // halves
#define W2_LD    24             // halves
#define YS_LD    132            // floats
#define OFF_ST   0                            // sT[64][136] half    17408
#define OFF_VT   17408                        // vT[96][136] half    26112
#define OFF_XT   43520                        // XT[80][136] half    21760
#define OFF_WB   65280                        // WB[64][72] half      9216
#define OFF_YS   74496                        // YS 64 cols x 132 f  33792
#define SMEM_TOTAL 108288

// ================= preprocessed weights (gmem) =================
__device__ __half d_Wcat[KTOT * 64];        // [k][p]
__device__ __half d_Wc1 [64 * 1024];        // [u][q*32+v]
__device__ __half d_Wc2 [PGRPS * 80 * 16];  // [(pg*80 + m*16 + pi)][r]
__device__ unsigned short d_pairs [KTOT];
__device__ unsigned short d_pairs2[NPAIR2];
__device__ float d_g[32];

#define N_CAT (KTOT * 64)
#define B_C1  N_CAT
#define N_C1  (64 * 1024)
#define B_C2  (B_C1 + N_C1)
#define N_C2  (PGRPS * 80 * 16)
#define B_PR  (B_C2 + N_C2)
#define B_PR2 (B_PR + KTOT)
#define B_G   (B_PR2 + NPAIR2)
#define N_ALL (B_G + 32)

// ================= prep kernel =================
__device__ __forceinline__ void pair_decode(int k, int width, int& u, int& v) {
    int uu = 0, rem = k;
    while (rem >= width - uu) { rem -= width - uu; uu++; }
    u = uu; v = uu + rem;
}

__global__ void prep_all(const float* __restrict__ gates, const float* __restrict__ Wss0,
                         const float* __restrict__ Wsv1, const float* __restrict__ Wvv0,
                         const float* __restrict__ Wvv2) {
    int idx = blockIdx.x * blockDim.x + threadIdx.x;
    if (idx >= N_ALL) return;
    const float c0  = rsqrtf(5120.f);
    const float cvv = c0 * rsqrtf(3.f);
    const float c1  = rsqrtf(2048.f);
    const float c2  = 0.03125f;
    const float is2 = 0.70710678118654752f;
    const float is6 = 0.40824829046386302f;

    if (idx < N_CAT) {
        int k = idx >> 6, p = idx & 63;
        float val = 0.f;
        if (k < 2080) {
            int u, v; pair_decode(k, 64, u, v);
            val = c0 * Wss0[(u * 64 + v) * 64 + p];
            if (u != v) val += c0 * Wss0[(v * 64 + u) * 64 + p];
        } else if (k < 2608) {
            int u, v; pair_decode(k - 2080, 32, u, v);
            val = cvv * Wvv0[(u * 32 + v) * 64 + p];
            if (u != v) val += cvv * Wvv0[(v * 32 + u) * 64 + p];
        }
        d_Wcat[idx] = __float2half_rn(val);
    } else if (idx < B_C2) {
        int o = idx - B_C1;
        int u = o >> 10, n = o & 1023;
        int q = n >> 5, v = n & 31;
        d_Wc1[o] = __float2half_rn(c1 * Wsv1[u * 1024 + v * 32 + q]);
    } else if (idx < B_PR) {
        int o = idx - B_C2;
        int k2 = o >> 4, r = o & 15;
        int pg = k2 / 80, rem = k2 % 80;
        int m = rem >> 4, pi = rem & 15;
        int pair = pg * 16 + pi;
        int u, v; pair_decode(pair, 32, u, v);
        float w = Wvv2[(u * 32 + v) * 16 + r];
        if (u != v) w += Wvv2[(v * 32 + u) * 16 + r];
        float sc = (m == 2) ? is6 : is2;
        d_Wc2[o] = __float2half_rn(c2 * sc * w);
    } else if (idx < B_PR2) {
        int k = idx - B_PR;
        unsigned short pr = 0xFFFF;
        if (k < 2080)      { int u, v; pair_decode(k, 64, u, v);        pr = (unsigned short)((u << 8) | v); }
        else if (k < 2608) { int u, v; pair_decode(k - 2080, 32, u, v); pr = (unsigned short)((u << 8) | v); }
        d_pairs[k] = pr;
    } else if (idx < B_G) {
        int k = idx - B_PR2;
        int u, v; pair_decode(k, 32, u, v);
        d_pairs2[k] = (unsigned short)((u << 8) | v);
    } else {
        int i = idx - B_G;
        d_g[i] = tanhf(gates[i]);
    }
}

// ================= main kernel =================
__global__ __launch_bounds__(THREADS, 2) void nltsq_main(
    const float* __restrict__ feats, float* __restrict__ out) {
    extern __shared__ char smem[];
    __half* sT = (__half*)(smem + OFF_ST);
    __half* vT = (__half*)(smem + OFF_VT);
    __half* XT = (__half*)(smem + OFF_XT);
    __half* WB = (__half*)(smem + OFF_WB);
    float*  YS = (float*)(smem + OFF_YS);

    const int tid  = threadIdx.x;
    const int wid  = tid >> 5;
    const int wrow = wid * 16;
    const int nodeBase = blockIdx.x * CTA_M;

    // ---- Phase A: load + activate (transposed fp16 stores) ----
    for (int idx = tid; idx < CTA_M * 160; idx += THREADS) {
        int n = idx / 160, c = idx % 160;
        float f = feats[(size_t)(nodeBase + n) * 160 + c];
        if (c < 64) {
            sT[c * LD + n] = __float2half_rn(tanhf(f));
        } else {
            int j = c - 64;
            vT[j * LD + n] = __float2half_rn(f * d_g[j / 3]);
        }
    }

    const int k4  = tid >> 2;   // k-row within chunk (0..63)
    const int qtr = tid & 3;    // m-quarter

    // prefetch W chunk 0 (Wcat)
    float4 w0, w1;
    {
        const float4* src = (const float4*)(d_Wcat + (size_t)k4 * 64 + qtr * 16);
        w0 = src[0]; w1 = src[1];
    }
    __syncthreads();

    // ======== GEMM 0: out0[128x64] = X[128x2624] @ Wcat ========
    {
        wmma::fragment<wmma::accumulator, 16, 16, 16, float> acc[4];
        #pragma unroll
        for (int nt = 0; nt < 4; nt++) wmma::fill_fragment(acc[nt], 0.f);

        for (int kc = 0; kc < KCH0; kc++) {
            // store prefetched W chunk
            {
                float4* dst = (float4*)(WB + k4 * WB_LD + qtr * 16);
                dst[0] = w0; dst[1] = w1;
            }
            // build X row k4, m-quarter qtr
            int kglob = kc * 64 + k4;
            unsigned int pr = d_pairs[kglob];
            int u = pr >> 8, v = pr & 255;
            __half2* xrow = (__half2*)(XT + k4 * LD + qtr * 32);
            if (kglob < 2080) {
                const __half2* su = (const __half2*)(sT + u * LD + qtr * 32);
                const __half2* sv = (const __half2*)(sT + v * LD + qtr * 32);
                #pragma unroll
                for (int i = 0; i < 16; i++) xrow[i] = __hmul2(su[i], sv[i]);
            } else if (kglob < 2608) {
                const __half2* a0 = (const __half2*)(vT + (u * 3 + 0) * LD + qtr * 32);
                const __half2* a1 = (const __half2*)(vT + (u * 3 + 1) * LD + qtr * 32);
                const __half2* a2 = (const __half2*)(vT + (u * 3 + 2) * LD + qtr * 32);
                const __half2* b0 = (const __half2*)(vT + (v * 3 + 0) * LD + qtr * 32);
                const __half2* b1 = (const __half2*)(vT + (v * 3 + 1) * LD + qtr * 32);
                const __half2* b2 = (const __half2*)(vT + (v * 3 + 2) * LD + qtr * 32);
                #pragma unroll
                for (int i = 0; i < 16; i++)
                    xrow[i] = __hfma2(a0[i], b0[i], __hfma2(a1[i], b1[i], __hmul2(a2[i], b2[i])));
            } else {
                #pragma unroll
                for (int i = 0; i < 16; i++) xrow[i] = __half2half2(__half(0.f));
            }
            // prefetch next W chunk
            if (kc + 1 < KCH0) {
                const float4* src = (const float4*)(d_Wcat + (size_t)(kc + 1) * 64 * 64
                                                    + (size_t)k4 * 64 + qtr * 16);
                w0 = src[0]; w1 = src[1];
            }
            __syncthreads();
            #pragma unroll
            for (int ks = 0; ks < 4; ks++) {
                wmma::fragment<wmma::matrix_a, 16, 16, 16, __half, wmma::col_major> a;
                wmma::load_matrix_sync(a, XT + ks * 16 * LD + wrow, LD);
                #pragma unroll
                for (int nt = 0; nt < 4; nt++) {
                    wmma::fragment<wmma::matrix_b, 16, 16, 16, __half, wmma::row_major> b;
                    wmma::load_matrix_sync(b, WB + ks * 16 * WB_LD + nt * 16, WB_LD);
                    wmma::mma_sync(acc[nt], a, b, acc[nt]);
                }
            }
            __syncthreads();
        }
        #pragma unroll
        for (int nt = 0; nt < 4; nt++)
            wmma::store_matrix_sync(out + (size_t)(nodeBase + wrow) * DOUT + nt * 16,
                                    acc[nt], DOUT, wmma::mem_row_major);
    }

    // ---- cache this thread's v-column (node tid>>1) as 48 half2 ----
    const int en = tid >> 1;
    const int qsel = tid & 1;
    uint32_t vc[48];
    #pragma unroll
    for (int r = 0; r < 48; r++) {
        __half lo = vT[(2 * r) * LD + en];
        __half hi = vT[(2 * r + 1) * LD + en];
        vc[r] = (uint32_t)__half_as_ushort(lo) | ((uint32_t)__half_as_ushort(hi) << 16);
    }
    float* orow = out + (size_t)(nodeBase + en) * DOUT;

    // prefetch Wc1 chunk 0
    {
        const float4* src = (const float4*)(d_Wc1 + (size_t)k4 * 1024 + qtr * 16);
        w0 = src[0]; w1 = src[1];
    }

    // ======== GEMM 1: Y = sH @ Wc1 in 16 chunks of 64 cols; out1 = Y . v ========
    for (int nc = 0; nc < 16; nc++) {
        {
            float4* dst = (float4*)(WB + k4 * WB_LD + qtr * 16);
            dst[0] = w0; dst[1] = w1;
        }
        if (nc + 1 < 16) {
            const float4* src = (const float4*)(d_Wc1 + (size_t)k4 * 1024 + (nc + 1) * 64 + qtr * 16);
            w0 = src[0]; w1 = src[1];
        }
        __syncthreads();
        #pragma unroll
        for (int nt = 0; nt < 4; nt++) {
            wmma::fragment<wmma::accumulator, 16, 16, 16, float> acc;
            wmma::fill_fragment(acc, 0.f);
            #pragma unroll
            for (int ks = 0; ks < 4; ks++) {
                wmma::fragment<wmma::matrix_a, 16, 16, 16, __half, wmma::col_major> a;
                wmma::fragment<wmma::matrix_b, 16, 16, 16, __half, wmma::row_major> b;
                wmma::load_matrix_sync(a, sT + ks * 16 * LD + wrow, LD);
                wmma::load_matrix_sync(b, WB + ks * 16 * WB_LD + nt * 16, WB_LD);
                wmma::mma_sync(acc, a, b, acc);
            }
            wmma::store_matrix_sync(YS + wrow + (nt * 16) * YS_LD, acc, YS_LD,
                                    wmma::mem_col_major);
        }
        __syncthreads();
        // epilogue: node en, q = nc*2 + qsel
        {
            float a0 = 0.f, a1s = 0.f, a2 = 0.f;
            const float* ycol = YS + en + (qsel * 32) * YS_LD;
            #pragma unroll
            for (int v2 = 0; v2 < 16; v2++) {
                __half2 p0 = *(__half2*)&vc[3 * v2];
                __half2 p1 = *(__half2*)&vc[3 * v2 + 1];
                __half2 p2 = *(__half2*)&vc[3 * v2 + 2];
                float y0 = ycol[(2 * v2) * YS_LD];
                float y1 = ycol[(2 * v2 + 1) * YS_LD];
                a0  += y0 * __low2float(p0);  a1s += y0 * __high2float(p0); a2 += y0 * __low2float(p1);
                a0  += y1 * __high2float(p1); a1s += y1 * __low2float(p2);  a2 += y1 * __high2float(p2);
            }
            int q = nc * 2 + qsel;
            orow[64 + q * 3]     = a0;
            orow[64 + q * 3 + 1] = a1s;
            orow[64 + q * 3 + 2] = a2;
        }
    }

    // ======== GEMM 2: out2 via symmetric pair features ========
    {
        wmma::fragment<wmma::accumulator, 16, 16, 16, float> acc2[5];
        #pragma unroll
        for (int m = 0; m < 5; m++) wmma::fill_fragment(acc2[m], 0.f);

        const int pi = tid >> 4;      // pair in group (0..15)
        const int mh = tid & 15;      // m-chunk: 8 m's
        // prefetch Wc2 block 0 (80x16 half = 2560B; threads < 160)
        float4 w2;
        if (tid < 160) {
            const float4* src = (const float4*)(d_Wc2 + (size_t)(tid >> 1) * 16 + (tid & 1) * 8);
            w2 = src[0];
        }
        __half* w2h = WB + (tid >> 1) * W2_LD + (tid & 1) * 8;

        for (int pg = 0; pg < PGRPS; pg++) {
            if (tid < 160) *(float4*)w2h = w2;
            // build 5 feature rows for pair pi at m-chunk mh*8
            unsigned int pr = d_pairs2[pg * 16 + pi];
            int u = pr >> 8, v = pr & 255;
            const __half2* u0 = (const __half2*)(vT + (u * 3 + 0) * LD + mh * 8);
            const __half2* u1 = (const __half2*)(vT + (u * 3 + 1) * LD + mh * 8);
            const __half2* u2 = (const __half2*)(vT + (u * 3 + 2) * LD + mh * 8);
            const __half2* v0 = (const __half2*)(vT + (v * 3 + 0) * LD + mh * 8);
            const __half2* v1 = (const __half2*)(vT + (v * 3 + 1) * LD + mh * 8);
            const __half2* v2v = (const __half2*)(vT + (v * 3 + 2) * LD + mh * 8);
            __half2* x0 = (__half2*)(XT + (0 * 16 + pi) * LD + mh * 8);
            __half2* x1 = (__half2*)(XT + (1 * 16 + pi) * LD + mh * 8);
            __half2* x2 = (__half2*)(XT + (2 * 16 + pi) * LD + mh * 8);
            __half2* x3 = (__half2*)(XT + (3 * 16 + pi) * LD + mh * 8);
            __half2* x4 = (__half2*)(XT + (4 * 16 + pi) * LD + mh * 8);
            #pragma unroll
            for (int i = 0; i < 4; i++) {
                __half2 a0 = u0[i], a1 = u1[i], a2 = u2[i];
                __half2 b0 = v0[i], b1 = v1[i], b2 = v2v[i];
                __half2 aa = __hmul2(a0, b0);
                __half2 bb = __hmul2(a1, b1);
                __half2 cc = __hmul2(a2, b2);
                x0[i] = __hfma2(a0, b1, __hmul2(a1, b0));
                x1[i] = __hfma2(a1, b2, __hmul2(a2, b1));
                x2[i] = __hsub2(__hsub2(__hadd2(cc, cc), aa), bb);
                x3[i] = __hfma2(a0, b2, __hmul2(a2, b0));
                x4[i] = __hsub2(aa, bb);
            }
            if (pg + 1 < PGRPS && tid < 160) {
                const float4* src = (const float4*)(d_Wc2 + (size_t)(pg + 1) * 80 * 16
                                                    + (size_t)(tid >> 1) * 16 + (tid & 1) * 8);
                w2 = src[0];
            }
            __syncthreads();
            #pragma unroll
            for (int mf = 0; mf < 5; mf++) {
                wmma::fragment<wmma::matrix_a, 16, 16, 16, __half, wmma::col_major> a;
                wmma::fragment<wmma::matrix_b, 16, 16, 16, __half, wmma::row_major> b;
                wmma::load_matrix_sync(a, XT + (mf * 16) * LD + wrow, LD);
                wmma::load_matrix_sync(b, WB + (mf * 16) * W2_LD, W2_LD);
                wmma::mma_sync(acc2[mf], a, b, acc2[mf]);
            }
            __syncthreads();
        }
        // stage + write out2 in two passes (YS holds 64 cols)
        #pragma unroll
        for (int m = 0; m < 3; m++)
            wmma::store_matrix_sync(YS + wrow + (m * 16) * YS_LD, acc2[m], YS_LD,
                                    wmma::mem_col_major);
        __syncthreads();
        for (int idx = tid; idx < CTA_M * 48; idx += THREADS) {
            int n = idx / 48, c = idx % 48;
            int m = c >> 4, r = c & 15;
            out[(size_t)(nodeBase + n) * DOUT + 160 + r * 5 + m] = YS[n + c * YS_LD];
        }
        __syncthreads();
        #pragma unroll
        for (int m = 3; m < 5; m++)
            wmma::store_matrix_sync(YS + wrow + ((m - 3) * 16) * YS_LD, acc2[m], YS_LD,
                                    wmma::mem_col_major);
        __syncthreads();
        for (int idx = tid; idx < CTA_M * 32; idx += THREADS) {
            int n = idx / 32, c = idx % 32;
            int m = 3 + (c >> 4), r = c & 15;
            out[(size_t)(nodeBase + n) * DOUT + 160 + r * 5 + m] = YS[n + c * YS_LD];
        }
    }
}

// ================= launch =================
extern "C" void kernel_launch(void* const* d_in, const int* in_sizes, int n_in,
                              void* d_out, int out_size) {
    const float* feats = (const float*)d_in[0];
    const float* gates = (const float*)d_in[1];
    const float* Wss0  = (const float*)d_in[2];
    const float* Wsv1  = (const float*)d_in[3];
    const float* Wvv0  = (const float*)d_in[4];
    const float* Wvv2  = (const float*)d_in[5];
    float* out = (float*)d_out;

    static bool attr_set = false;
    if (!attr_set) {
        cudaFuncSetAttribute(nltsq_main, cudaFuncAttributeMaxDynamicSharedMemorySize, SMEM_TOTAL);
        attr_set = true;
    }

    prep_all<<<(N_ALL + 255) / 256, 256>>>(gates, Wss0, Wsv1, Wvv0, Wvv2);
    nltsq_main<<<NODES / CTA_M, THREADS, SMEM_TOTAL>>>(feats, out);
}

// round 7
// speedup vs baseline: 5.5661x; 1.0544x over previous
#include <cuda_runtime.h>
#include <cuda_fp16.h>
#include <mma.h>
#include <math.h>
#include <stdint.h>

using namespace nvcuda;

// ================= problem constants =================
#define NODES   32768
#define CTA_M   128
#define THREADS 256
#define DOUT    240
#define KTOT    2624            // 2080 ss + 528 vv + 16 pad = 41*64
#define KCH0    41
#define NPAIR2  528
#define PGRPS   33              // 528/16

// ================= smem layout =================
#define LD       136            // halves
#define WB_LD    72             // halves
#define W2_LD    24             // halves
#define YS_LD    132            // floats

#define OFF_ST   0              // sT[64][136]  half  17408
#define OFF_VT   17408          // vT[96][136]  half  26112
#define OFF_C    43520          // union region       53248
#define SMEM_TOTAL 96768

// region C sub-layouts (phase-exclusive)
#define C_XT0   (OFF_C)             // GEMM0 X tile buf0   17408
#define C_XT1   (OFF_C + 17408)     //              buf1   17408
#define C_WB0   (OFF_C + 34816)     // GEMM0 W tile buf0    9216
#define C_WB1   (OFF_C + 44032)     //              buf1    9216
#define C1_WB0  (OFF_C)             // GEMM1 W buf0         9216
#define C1_WB1  (OFF_C + 9216)      //         buf1         9216
#define C1_YS   (OFF_C + 18432)     // GEMM1 staging       33792
#define C2_XT0  (OFF_C)             // GEMM2 feat buf0     21760
#define C2_XT1  (OFF_C + 21760)     //            buf1     21760
#define C2_WB0  (OFF_C + 43520)     // GEMM2 W buf0         3840
#define C2_WB1  (OFF_C + 47360)     //          buf1        3840
#define C2_YS   (OFF_C)             // GEMM2 staging (post-loop) 42240

// ================= preprocessed weights (gmem) =================
__device__ __half d_Wcat[KTOT * 64];        // [k][p]
__device__ __half d_Wc1 [64 * 1024];        // [u][q*32+v]
__device__ __half d_Wc2 [PGRPS * 80 * 16];  // [(pg*80 + m*16 + pi)][r]
__device__ unsigned short d_pairs [KTOT];
__device__ unsigned short d_pairs2[NPAIR2];
__device__ float d_g[32];

#define N_CAT (KTOT * 64)
#define B_C1  N_CAT
#define N_C1  (64 * 1024)
#define B_C2  (B_C1 + N_C1)
#define N_C2  (PGRPS * 80 * 16)
#define B_PR  (B_C2 + N_C2)
#define B_PR2 (B_PR + KTOT)
#define B_G   (B_PR2 + NPAIR2)
#define N_ALL (B_G + 32)

// ================= prep kernel =================
__device__ __forceinline__ void pair_decode(int k, int width, int& u, int& v) {
    int uu = 0, rem = k;
    while (rem >= width - uu) { rem -= width - uu; uu++; }
    u = uu; v = uu + rem;
}

__global__ void prep_all(const float* __restrict__ gates, const float* __restrict__ Wss0,
                         const float* __restrict__ Wsv1, const float* __restrict__ Wvv0,
                         const float* __restrict__ Wvv2) {
    int idx = blockIdx.x * blockDim.x + threadIdx.x;
    if (idx >= N_ALL) return;
    const float c0  = rsqrtf(5120.f);
    const float cvv = c0 * rsqrtf(3.f);
    const float c1  = rsqrtf(2048.f);
    const float c2  = 0.03125f;
    const float is2 = 0.70710678118654752f;
    const float is6 = 0.40824829046386302f;

    if (idx < N_CAT) {
        int k = idx >> 6, p = idx & 63;
        float val = 0.f;
        if (k < 2080) {
            int u, v; pair_decode(k, 64, u, v);
            val = c0 * Wss0[(u * 64 + v) * 64 + p];
            if (u != v) val += c0 * Wss0[(v * 64 + u) * 64 + p];
        } else if (k < 2608) {
            int u, v; pair_decode(k - 2080, 32, u, v);
            val = cvv * Wvv0[(u * 32 + v) * 64 + p];
            if (u != v) val += cvv * Wvv0[(v * 32 + u) * 64 + p];
        }
        d_Wcat[idx] = __float2half_rn(val);
    } else if (idx < B_C2) {
        int o = idx - B_C1;
        int u = o >> 10, n = o & 1023;
        int q = n >> 5, v = n & 31;
        d_Wc1[o] = __float2half_rn(c1 * Wsv1[u * 1024 + v * 32 + q]);
    } else if (idx < B_PR) {
        int o = idx - B_C2;
        int k2 = o >> 4, r = o & 15;
        int pg = k2 / 80, rem = k2 % 80;
        int m = rem >> 4, pi = rem & 15;
        int pair = pg * 16 + pi;
        int u, v; pair_decode(pair, 32, u, v);
        float w = Wvv2[(u * 32 + v) * 16 + r];
        if (u != v) w += Wvv2[(v * 32 + u) * 16 + r];
        float sc = (m == 2) ? is6 : is2;
        d_Wc2[o] = __float2half_rn(c2 * sc * w);
    } else if (idx < B_PR2) {
        int k = idx - B_PR;
        unsigned short pr = 0xFFFF;
        if (k < 2080)      { int u, v; pair_decode(k, 64, u, v);        pr = (unsigned short)((u << 8) | v); }
        else if (k < 2608) { int u, v; pair_decode(k - 2080, 32, u, v); pr = (unsigned short)((u << 8) | v); }
        d_pairs[k] = pr;
    } else if (idx < B_G) {
        int k = idx - B_PR2;
        int u, v; pair_decode(k, 32, u, v);
        d_pairs2[k] = (unsigned short)((u << 8) | v);
    } else {
        int i = idx - B_G;
        d_g[i] = tanhf(gates[i]);
    }
}

// ================= main kernel =================
__global__ __launch_bounds__(THREADS, 2) void nltsq_main(
    const float* __restrict__ feats, float* __restrict__ out) {
    extern __shared__ char smem[];
    __half* sT = (__half*)(smem + OFF_ST);
    __half* vT = (__half*)(smem + OFF_VT);

    const int tid  = threadIdx.x;
    const int wid  = tid >> 5;
    const int lane = tid & 31;
    const int wrow = wid * 16;
    const int nodeBase = blockIdx.x * CTA_M;

    // ---- Phase A: load + activate (transposed fp16) ----
    for (int idx = tid; idx < CTA_M * 160; idx += THREADS) {
        int n = idx / 160, c = idx % 160;
        float f = feats[(size_t)(nodeBase + n) * 160 + c];
        if (c < 64) {
            sT[c * LD + n] = __float2half_rn(tanhf(f));
        } else {
            int j = c - 64;
            vT[j * LD + n] = __float2half_rn(f * d_g[j / 3]);
        }
    }

    const int k4  = tid >> 2;   // 0..63
    const int qtr = tid & 3;    // m-quarter

    float4 w0, w1;
    {   // prefetch Wcat chunk 0
        const float4* src = (const float4*)(d_Wcat + (size_t)k4 * 64 + qtr * 16);
        w0 = src[0]; w1 = src[1];
    }
    __syncthreads();

    // ======== GEMM 0: out0[128x64] = X[128x2624] @ Wcat (single-sync pipeline) ========
    {
        wmma::fragment<wmma::accumulator, 16, 16, 16, float> acc[4];
        #pragma unroll
        for (int nt = 0; nt < 4; nt++) wmma::fill_fragment(acc[nt], 0.f);

        for (int kc = 0; kc < KCH0; kc++) {
            __half* XT = (__half*)(smem + ((kc & 1) ? C_XT1 : C_XT0));
            __half* WB = (__half*)(smem + ((kc & 1) ? C_WB1 : C_WB0));
            {   // store prefetched W chunk
                float4* dst = (float4*)(WB + k4 * WB_LD + qtr * 16);
                dst[0] = w0; dst[1] = w1;
            }
            // build X row k4, m-quarter qtr
            int kglob = kc * 64 + k4;
            unsigned int pr = d_pairs[kglob];
            int u = pr >> 8, v = pr & 255;
            __half2* xrow = (__half2*)(XT + k4 * LD + qtr * 32);
            if (kglob < 2080) {
                const __half2* su = (const __half2*)(sT + u * LD + qtr * 32);
                const __half2* sv = (const __half2*)(sT + v * LD + qtr * 32);
                #pragma unroll
                for (int i = 0; i < 16; i++) xrow[i] = __hmul2(su[i], sv[i]);
            } else if (kglob < 2608) {
                const __half2* a0 = (const __half2*)(vT + (u * 3 + 0) * LD + qtr * 32);
                const __half2* a1 = (const __half2*)(vT + (u * 3 + 1) * LD + qtr * 32);
                const __half2* a2 = (const __half2*)(vT + (u * 3 + 2) * LD + qtr * 32);
                const __half2* b0 = (const __half2*)(vT + (v * 3 + 0) * LD + qtr * 32);
                const __half2* b1 = (const __half2*)(vT + (v * 3 + 1) * LD + qtr * 32);
                const __half2* b2 = (const __half2*)(vT + (v * 3 + 2) * LD + qtr * 32);
                #pragma unroll
                for (int i = 0; i < 16; i++)
                    xrow[i] = __hfma2(a0[i], b0[i], __hfma2(a1[i], b1[i], __hmul2(a2[i], b2[i])));
            } else {
                #pragma unroll
                for (int i = 0; i < 16; i++) xrow[i] = __half2half2(__half(0.f));
            }
            if (kc + 1 < KCH0) {   // prefetch next W chunk
                const float4* src = (const float4*)(d_Wcat + (size_t)(kc + 1) * 64 * 64
                                                    + (size_t)k4 * 64 + qtr * 16);
                w0 = src[0]; w1 = src[1];
            }
            __syncthreads();        // ONLY sync: tiles ready -> mma; WAR covered by next iter's sync
            #pragma unroll
            for (int ks = 0; ks < 4; ks++) {
                wmma::fragment<wmma::matrix_a, 16, 16, 16, __half, wmma::col_major> a;
                wmma::load_matrix_sync(a, XT + ks * 16 * LD + wrow, LD);
                #pragma unroll
                for (int nt = 0; nt < 4; nt++) {
                    wmma::fragment<wmma::matrix_b, 16, 16, 16, __half, wmma::row_major> b;
                    wmma::load_matrix_sync(b, WB + ks * 16 * WB_LD + nt * 16, WB_LD);
                    wmma::mma_sync(acc[nt], a, b, acc[nt]);
                }
            }
        }
        #pragma unroll
        for (int nt = 0; nt < 4; nt++)
            wmma::store_matrix_sync(out + (size_t)(nodeBase + wrow) * DOUT + nt * 16,
                                    acc[nt], DOUT, wmma::mem_row_major);
    }

    // ---- cache own-strip node's v-column (node en) as 48 half2 ----
    const int en   = wrow + (lane & 15);    // node within OWN warp's strip
    const int qsel = lane >> 4;
    uint32_t vc[48];
    #pragma unroll
    for (int r = 0; r < 48; r++) {
        __half lo = vT[(2 * r) * LD + en];
        __half hi = vT[(2 * r + 1) * LD + en];
        vc[r] = (uint32_t)__half_as_ushort(lo) | ((uint32_t)__half_as_ushort(hi) << 16);
    }
    float* orow = out + (size_t)(nodeBase + en) * DOUT;

    {   // prefetch Wc1 chunk 0
        const float4* src = (const float4*)(d_Wc1 + (size_t)k4 * 1024 + qtr * 16);
        w0 = src[0]; w1 = src[1];
    }
    __syncthreads();   // GEMM0 mma fully done before region C reuse

    // ======== GEMM 1: Y = sH @ Wc1 (16 chunks of 64 cols); out1 = Y . v ========
    {
        wmma::fragment<wmma::matrix_a, 16, 16, 16, __half, wmma::col_major> a1[4];
        #pragma unroll
        for (int ks = 0; ks < 4; ks++)
            wmma::load_matrix_sync(a1[ks], sT + ks * 16 * LD + wrow, LD);
        float* YS = (float*)(smem + C1_YS);

        for (int nc = 0; nc < 16; nc++) {
            __half* WB = (__half*)(smem + ((nc & 1) ? C1_WB1 : C1_WB0));
            {
                float4* dst = (float4*)(WB + k4 * WB_LD + qtr * 16);
                dst[0] = w0; dst[1] = w1;
            }
            if (nc + 1 < 16) {
                const float4* src = (const float4*)(d_Wc1 + (size_t)k4 * 1024
                                                    + (nc + 1) * 64 + qtr * 16);
                w0 = src[0]; w1 = src[1];
            }
            __syncthreads();
            #pragma unroll
            for (int nt = 0; nt < 4; nt++) {
                wmma::fragment<wmma::accumulator, 16, 16, 16, float> acc;
                wmma::fill_fragment(acc, 0.f);
                #pragma unroll
                for (int ks = 0; ks < 4; ks++) {
                    wmma::fragment<wmma::matrix_b, 16, 16, 16, __half, wmma::row_major> b;
                    wmma::load_matrix_sync(b, WB + ks * 16 * WB_LD + nt * 16, WB_LD);
                    wmma::mma_sync(acc, a1[ks], b, acc);
                }
                wmma::store_matrix_sync(YS + wrow + (nt * 16) * YS_LD, acc, YS_LD,
                                        wmma::mem_col_major);
            }
            __syncwarp();   // own-strip YS visible to own warp
            {   // epilogue: node en (own strip), q = nc*2 + qsel
                float a0 = 0.f, a1s = 0.f, a2 = 0.f;
                const float* ycol = YS + en + (qsel * 32) * YS_LD;
                #pragma unroll
                for (int v2 = 0; v2 < 16; v2++) {
                    __half2 p0 = *(__half2*)&vc[3 * v2];
                    __half2 p1 = *(__half2*)&vc[3 * v2 + 1];
                    __half2 p2 = *(__half2*)&vc[3 * v2 + 2];
                    float y0 = ycol[(2 * v2) * YS_LD];
                    float y1 = ycol[(2 * v2 + 1) * YS_LD];
                    a0  += y0 * __low2float(p0);  a1s += y0 * __high2float(p0); a2 += y0 * __low2float(p1);
                    a0  += y1 * __high2float(p1); a1s += y1 * __low2float(p2);  a2 += y1 * __high2float(p2);
                }
                int q = nc * 2 + qsel;
                orow[64 + q * 3]     = a0;
                orow[64 + q * 3 + 1] = a1s;
                orow[64 + q * 3 + 2] = a2;
            }
            __syncwarp();   // epilogue reads done before next chunk's YS stores
        }
    }
    __syncthreads();   // GEMM1 done before region C reuse

    // ======== GEMM 2: out2 via symmetric pair features ========
    {
        wmma::fragment<wmma::accumulator, 16, 16, 16, float> acc2[5];
        #pragma unroll
        for (int m = 0; m < 5; m++) wmma::fill_fragment(acc2[m], 0.f);

        const int pi = tid >> 4;      // pair in group (0..15)
        const int mh = tid & 15;      // m-chunk of 8 nodes
        float4 w2;
        if (tid < 160) {
            const float4* src = (const float4*)(d_Wc2 + (size_t)(tid >> 1) * 16 + (tid & 1) * 8);
            w2 = src[0];
        }

        for (int pg = 0; pg < PGRPS; pg++) {
            __half* XT = (__half*)(smem + ((pg & 1) ? C2_XT1 : C2_XT0));
            __half* WB = (__half*)(smem + ((pg & 1) ? C2_WB1 : C2_WB0));
            if (tid < 160) *(float4*)(WB + (tid >> 1) * W2_LD + (tid & 1) * 8) = w2;
            unsigned int pr = d_pairs2[pg * 16 + pi];
            int u = pr >> 8, v = pr & 255;
            const __half2* u0 = (const __half2*)(vT + (u * 3 + 0) * LD + mh * 8);
            const __half2* u1 = (const __half2*)(vT + (u * 3 + 1) * LD + mh * 8);
            const __half2* u2 = (const __half2*)(vT + (u * 3 + 2) * LD + mh * 8);
            const __half2* v0 = (const __half2*)(vT + (v * 3 + 0) * LD + mh * 8);
            const __half2* v1 = (const __half2*)(vT + (v * 3 + 1) * LD + mh * 8);
            const __half2* v2v = (const __half2*)(vT + (v * 3 + 2) * LD + mh * 8);
            __half2* x0 = (__half2*)(XT + (0 * 16 + pi) * LD + mh * 8);
            __half2* x1 = (__half2*)(XT + (1 * 16 + pi) * LD + mh * 8);
            __half2* x2 = (__half2*)(XT + (2 * 16 + pi) * LD + mh * 8);
            __half2* x3 = (__half2*)(XT + (3 * 16 + pi) * LD + mh * 8);
            __half2* x4 = (__half2*)(XT + (4 * 16 + pi) * LD + mh * 8);
            #pragma unroll
            for (int i = 0; i < 4; i++) {
                __half2 a0 = u0[i], a1 = u1[i], a2 = u2[i];
                __half2 b0 = v0[i], b1 = v1[i], b2 = v2v[i];
                __half2 aa = __hmul2(a0, b0);
                __half2 bb = __hmul2(a1, b1);
                __half2 cc = __hmul2(a2, b2);
                x0[i] = __hfma2(a0, b1, __hmul2(a1, b0));
                x1[i] = __hfma2(a1, b2, __hmul2(a2, b1));
                x2[i] = __hsub2(__hsub2(__hadd2(cc, cc), aa), bb);
                x3[i] = __hfma2(a0, b2, __hmul2(a2, b0));
                x4[i] = __hsub2(aa, bb);
            }
            if (pg + 1 < PGRPS && tid < 160) {
                const float4* src = (const float4*)(d_Wc2 + (size_t)(pg + 1) * 80 * 16
                                                    + (size_t)(tid >> 1) * 16 + (tid & 1) * 8);
                w2 = src[0];
            }
            __syncthreads();
            #pragma unroll
            for (int mf = 0; mf < 5; mf++) {
                wmma::fragment<wmma::matrix_a, 16, 16, 16, __half, wmma::col_major> a;
                wmma::fragment<wmma::matrix_b, 16, 16, 16, __half, wmma::row_major> b;
                wmma::load_matrix_sync(a, XT + (mf * 16) * LD + wrow, LD);
                wmma::load_matrix_sync(b, WB + (mf * 16) * W2_LD, W2_LD);
                wmma::mma_sync(acc2[mf], a, b, acc2[mf]);
            }
        }
        __syncthreads();   // all mma done before staging overwrites region C
        float* YS = (float*)(smem + C2_YS);
        #pragma unroll
        for (int m = 0; m < 5; m++)
            wmma::store_matrix_sync(YS + wrow + (m * 16) * YS_LD, acc2[m], YS_LD,
                                    wmma::mem_col_major);
        __syncthreads();
        for (int idx = tid; idx < CTA_M * 80; idx += THREADS) {
            int n = idx / 80, c = idx % 80;
            int m = c >> 4, r = c & 15;
            out[(size_t)(nodeBase + n) * DOUT + 160 + r * 5 + m] = YS[n + c * YS_LD];
        }
    }
}

// ================= launch =================
extern "C" void kernel_launch(void* const* d_in, const int* in_sizes, int n_in,
                              void* d_out, int out_size) {
    const float* feats = (const float*)d_in[0];
    const float* gates = (const float*)d_in[1];
    const float* Wss0  = (const float*)d_in[2];
    const float* Wsv1  = (const float*)d_in[3];
    const float* Wvv0  = (const float*)d_in[4];
    const float* Wvv2  = (const float*)d_in[5];
    float* out = (float*)d_out;

    static bool attr_set = false;
    if (!attr_set) {
        cudaFuncSetAttribute(nltsq_main, cudaFuncAttributeMaxDynamicSharedMemorySize, SMEM_TOTAL);
        attr_set = true;
    }

    prep_all<<<(N_ALL + 255) / 256, 256>>>(gates, Wss0, Wsv1, Wvv0, Wvv2);
    nltsq_main<<<NODES / CTA_M, THREADS, SMEM_TOTAL>>>(feats, out);
}

// round 9
// speedup vs baseline: 7.8875x; 1.4170x over previous
#include <cuda_runtime.h>
#include <cuda_fp16.h>
#include <mma.h>
#include <math.h>
#include <stdint.h>

using namespace nvcuda;

// ================= problem constants =================
#define NODES   32768
#define CTA_M   128
#define THREADS 256
#define DOUT    240
#define KTOT    2624            // 2080 ss + 528 vv + 16 pad = 41*64
#define KCH0    41
#define NPAIR2  528
#define PGRPS   33              // 528/16

// ================= smem layout =================
#define LD       136            // halves
#define WB_LD    72             // halves
#define W2_LD    24             // halves
#define YS_LD    132            // floats (GEMM2 col-major staging)
#define Y1_LD    68             // floats (GEMM1 row-major staging)

#define OFF_ST   0              // sT[64][136]  half  17408
#define OFF_VT   17408          // vT[96][136]  half  26112
#define OFF_C    43520          // union region       53248
#define SMEM_TOTAL 96768

// region C sub-layouts (phase-exclusive)
#define C_XT0   (OFF_C)             // GEMM0 X tile buf0   17408
#define C_XT1   (OFF_C + 17408)     //              buf1   17408
#define C_WB0   (OFF_C + 34816)     // GEMM0 W tile buf0    9216
#define C_WB1   (OFF_C + 44032)     //              buf1    9216
#define C1_WB0  (OFF_C)             // GEMM1 W buf0         9216
#define C1_WB1  (OFF_C + 9216)      //         buf1         9216
#define C1_YS   (OFF_C + 18432)     // GEMM1 staging (row-major 128x68 f) 34816
#define C2_XT0  (OFF_C)             // GEMM2 feat buf0     21760
#define C2_XT1  (OFF_C + 21760)     //            buf1     21760
#define C2_WB0  (OFF_C + 43520)     // GEMM2 W buf0         3840
#define C2_WB1  (OFF_C + 47360)     //          buf1        3840
#define C2_YS   (OFF_C)             // GEMM2 staging (post-loop) 42240

struct alignas(16) H8 { __half2 h[4]; };

// ================= preprocessed weights (gmem) =================
__device__ __half d_Wcat[KTOT * 64];        // [k][p]
__device__ __half d_Wc1 [64 * 1024];        // [u][q*32+v]
__device__ __half d_Wc2 [PGRPS * 80 * 16];  // [(pg*80 + m*16 + pi)][r]
__device__ unsigned short d_pairs [KTOT];
__device__ unsigned short d_pairs2[NPAIR2];
__device__ float d_g[32];

#define N_CAT (KTOT * 64)
#define B_C1  N_CAT
#define N_C1  (64 * 1024)
#define B_C2  (B_C1 + N_C1)
#define N_C2  (PGRPS * 80 * 16)
#define B_PR  (B_C2 + N_C2)
#define B_PR2 (B_PR + KTOT)
#define B_G   (B_PR2 + NPAIR2)
#define N_ALL (B_G + 32)

// ================= prep kernel =================
__device__ __forceinline__ void pair_decode(int k, int width, int& u, int& v) {
    int uu = 0, rem = k;
    while (rem >= width - uu) { rem -= width - uu; uu++; }
    u = uu; v = uu + rem;
}

__global__ void prep_all(const float* __restrict__ gates, const float* __restrict__ Wss0,
                         const float* __restrict__ Wsv1, const float* __restrict__ Wvv0,
                         const float* __restrict__ Wvv2) {
    int idx = blockIdx.x * blockDim.x + threadIdx.x;
    if (idx >= N_ALL) return;
    const float c0  = rsqrtf(5120.f);
    const float cvv = c0 * rsqrtf(3.f);
    const float c1  = rsqrtf(2048.f);
    const float c2  = 0.03125f;
    const float is2 = 0.70710678118654752f;
    const float is6 = 0.40824829046386302f;

    if (idx < N_CAT) {
        int k = idx >> 6, p = idx & 63;
        float val = 0.f;
        if (k < 2080) {
            int u, v; pair_decode(k, 64, u, v);
            val = c0 * Wss0[(u * 64 + v) * 64 + p];
            if (u != v) val += c0 * Wss0[(v * 64 + u) * 64 + p];
        } else if (k < 2608) {
            int u, v; pair_decode(k - 2080, 32, u, v);
            val = cvv * Wvv0[(u * 32 + v) * 64 + p];
            if (u != v) val += cvv * Wvv0[(v * 32 + u) * 64 + p];
        }
        d_Wcat[idx] = __float2half_rn(val);
    } else if (idx < B_C2) {
        int o = idx - B_C1;
        int u = o >> 10, n = o & 1023;
        int q = n >> 5, v = n & 31;
        d_Wc1[o] = __float2half_rn(c1 * Wsv1[u * 1024 + v * 32 + q]);
    } else if (idx < B_PR) {
        int o = idx - B_C2;
        int k2 = o >> 4, r = o & 15;
        int pg = k2 / 80, rem = k2 % 80;
        int m = rem >> 4, pi = rem & 15;
        int pair = pg * 16 + pi;
        int u, v; pair_decode(pair, 32, u, v);
        float w = Wvv2[(u * 32 + v) * 16 + r];
        if (u != v) w += Wvv2[(v * 32 + u) * 16 + r];
        float sc = (m == 2) ? is6 : is2;
        d_Wc2[o] = __float2half_rn(c2 * sc * w);
    } else if (idx < B_PR2) {
        int k = idx - B_PR;
        unsigned short pr = 0xFFFF;
        if (k < 2080)      { int u, v; pair_decode(k, 64, u, v);        pr = (unsigned short)((u << 8) | v); }
        else if (k < 2608) { int u, v; pair_decode(k - 2080, 32, u, v); pr = (unsigned short)((u << 8) | v); }
        d_pairs[k] = pr;
    } else if (idx < B_G) {
        int k = idx - B_PR2;
        int u, v; pair_decode(k, 32, u, v);
        d_pairs2[k] = (unsigned short)((u << 8) | v);
    } else {
        int i = idx - B_G;
        d_g[i] = tanhf(gates[i]);
    }
}

// ================= main kernel =================
__global__ __launch_bounds__(THREADS, 2) void nltsq_main(
    const float* __restrict__ feats, float* __restrict__ out) {
    extern __shared__ char smem[];
    __half* sT = (__half*)(smem + OFF_ST);
    __half* vT = (__half*)(smem + OFF_VT);

    const int tid  = threadIdx.x;
    const int wid  = tid >> 5;
    const int lane = tid & 31;
    const int wrow = wid * 16;
    const int nodeBase = blockIdx.x * CTA_M;

    // ---- Phase A: load + activate (vectorized gmem reads, transposed fp16 stores) ----
    for (int idx = tid; idx < CTA_M * 40; idx += THREADS) {
        int n = idx / 40, c4 = idx % 40;
        float4 f = ((const float4*)(feats + (size_t)(nodeBase + n) * 160))[c4];
        int c = c4 * 4;
        if (c < 64) {
            sT[(c + 0) * LD + n] = __float2half_rn(tanhf(f.x));
            sT[(c + 1) * LD + n] = __float2half_rn(tanhf(f.y));
            sT[(c + 2) * LD + n] = __float2half_rn(tanhf(f.z));
            sT[(c + 3) * LD + n] = __float2half_rn(tanhf(f.w));
        } else {
            int j = c - 64;
            vT[(j + 0) * LD + n] = __float2half_rn(f.x * d_g[(j + 0) / 3]);
            vT[(j + 1) * LD + n] = __float2half_rn(f.y * d_g[(j + 1) / 3]);
            vT[(j + 2) * LD + n] = __float2half_rn(f.z * d_g[(j + 2) / 3]);
            vT[(j + 3) * LD + n] = __float2half_rn(f.w * d_g[(j + 3) / 3]);
        }
    }

    const int k4  = tid >> 2;   // 0..63
    const int qtr = tid & 3;    // m-quarter

    float4 w0, w1;
    {   // prefetch Wcat chunk 0
        const float4* src = (const float4*)(d_Wcat + (size_t)k4 * 64 + qtr * 16);
        w0 = src[0]; w1 = src[1];
    }
    __syncthreads();

    // ======== GEMM 0: out0[128x64] = X[128x2624] @ Wcat (single-sync pipeline) ========
    {
        // warp tile: (M32, N32). wm = wid>>1 (0..3), wn = wid&1 (0..1)
        const int mrow = (wid >> 1) * 32;
        const int ncol = (wid & 1) * 32;
        wmma::fragment<wmma::accumulator, 16, 16, 16, float> acc[2][2];
        #pragma unroll
        for (int i = 0; i < 2; i++)
            #pragma unroll
            for (int j = 0; j < 2; j++) wmma::fill_fragment(acc[i][j], 0.f);

        for (int kc = 0; kc < KCH0; kc++) {
            __half* XT = (__half*)(smem + ((kc & 1) ? C_XT1 : C_XT0));
            __half* WB = (__half*)(smem + ((kc & 1) ? C_WB1 : C_WB0));
            {   // store prefetched W chunk
                float4* dst = (float4*)(WB + k4 * WB_LD + qtr * 16);
                dst[0] = w0; dst[1] = w1;
            }
            // build X row k4, m-quarter qtr (vectorized)
            int kglob = kc * 64 + k4;
            unsigned int pr = d_pairs[kglob];
            int u = pr >> 8, v = pr & 255;
            H8* xrow = (H8*)(XT + k4 * LD + qtr * 32);
            if (kglob < 2080) {
                const H8* su = (const H8*)(sT + u * LD + qtr * 32);
                const H8* sv = (const H8*)(sT + v * LD + qtr * 32);
                #pragma unroll
                for (int i = 0; i < 4; i++) {
                    H8 a = su[i], b = sv[i], r;
                    #pragma unroll
                    for (int j = 0; j < 4; j++) r.h[j] = __hmul2(a.h[j], b.h[j]);
                    xrow[i] = r;
                }
            } else if (kglob < 2608) {
                const H8* a0 = (const H8*)(vT + (u * 3 + 0) * LD + qtr * 32);
                const H8* a1 = (const H8*)(vT + (u * 3 + 1) * LD + qtr * 32);
                const H8* a2 = (const H8*)(vT + (u * 3 + 2) * LD + qtr * 32);
                const H8* b0 = (const H8*)(vT + (v * 3 + 0) * LD + qtr * 32);
                const H8* b1 = (const H8*)(vT + (v * 3 + 1) * LD + qtr * 32);
                const H8* b2 = (const H8*)(vT + (v * 3 + 2) * LD + qtr * 32);
                #pragma unroll
                for (int i = 0; i < 4; i++) {
                    H8 x0 = a0[i], x1 = a1[i], x2 = a2[i];
                    H8 y0 = b0[i], y1 = b1[i], y2 = b2[i], r;
                    #pragma unroll
                    for (int j = 0; j < 4; j++)
                        r.h[j] = __hfma2(x0.h[j], y0.h[j],
                                 __hfma2(x1.h[j], y1.h[j], __hmul2(x2.h[j], y2.h[j])));
                    xrow[i] = r;
                }
            } else {
                H8 z;
                #pragma unroll
                for (int j = 0; j < 4; j++) z.h[j] = __half2half2(__half(0.f));
                #pragma unroll
                for (int i = 0; i < 4; i++) xrow[i] = z;
            }
            if (kc + 1 < KCH0) {   // prefetch next W chunk
                const float4* src = (const float4*)(d_Wcat + (size_t)(kc + 1) * 64 * 64
                                                    + (size_t)k4 * 64 + qtr * 16);
                w0 = src[0]; w1 = src[1];
            }
            __syncthreads();        // tiles ready -> mma; WAR covered by next iter's sync
            #pragma unroll
            for (int ks = 0; ks < 4; ks++) {
                wmma::fragment<wmma::matrix_a, 16, 16, 16, __half, wmma::col_major> a[2];
                wmma::fragment<wmma::matrix_b, 16, 16, 16, __half, wmma::row_major> b[2];
                #pragma unroll
                for (int i = 0; i < 2; i++)
                    wmma::load_matrix_sync(a[i], XT + ks * 16 * LD + mrow + i * 16, LD);
                #pragma unroll
                for (int j = 0; j < 2; j++)
                    wmma::load_matrix_sync(b[j], WB + ks * 16 * WB_LD + ncol + j * 16, WB_LD);
                #pragma unroll
                for (int i = 0; i < 2; i++)
                    #pragma unroll
                    for (int j = 0; j < 2; j++)
                        wmma::mma_sync(acc[i][j], a[i], b[j], acc[i][j]);
            }
        }
        #pragma unroll
        for (int i = 0; i < 2; i++)
            #pragma unroll
            for (int j = 0; j < 2; j++)
                wmma::store_matrix_sync(out + (size_t)(nodeBase + mrow + i * 16) * DOUT
                                        + ncol + j * 16, acc[i][j], DOUT, wmma::mem_row_major);
    }

    // ---- cache own-strip node's v-column (node en) as 48 half2 ----
    const int en   = wrow + (lane & 15);    // node within OWN warp's strip
    const int qsel = lane >> 4;
    uint32_t vc[48];
    #pragma unroll
    for (int r = 0; r < 48; r++) {
        __half lo = vT[(2 * r) * LD + en];
        __half hi = vT[(2 * r + 1) * LD + en];
        vc[r] = (uint32_t)__half_as_ushort(lo) | ((uint32_t)__half_as_ushort(hi) << 16);
    }
    float* orow = out + (size_t)(nodeBase + en) * DOUT;

    {   // prefetch Wc1 chunk 0
        const float4* src = (const float4*)(d_Wc1 + (size_t)k4 * 1024 + qtr * 16);
        w0 = src[0]; w1 = src[1];
    }
    __syncthreads();   // GEMM0 mma fully done before region C reuse

    // ======== GEMM 1: Y = sH @ Wc1 (16 chunks of 64 cols); out1 = Y . v ========
    {
        wmma::fragment<wmma::matrix_a, 16, 16, 16, __half, wmma::col_major> a1[4];
        #pragma unroll
        for (int ks = 0; ks < 4; ks++)
            wmma::load_matrix_sync(a1[ks], sT + ks * 16 * LD + wrow, LD);
        float* YS = (float*)(smem + C1_YS);     // row-major [128][Y1_LD]

        for (int nc = 0; nc < 16; nc++) {
            __half* WB = (__half*)(smem + ((nc & 1) ? C1_WB1 : C1_WB0));
            {
                float4* dst = (float4*)(WB + k4 * WB_LD + qtr * 16);
                dst[0] = w0; dst[1] = w1;
            }
            if (nc + 1 < 16) {
                const float4* src = (const float4*)(d_Wc1 + (size_t)k4 * 1024
                                                    + (nc + 1) * 64 + qtr * 16);
                w0 = src[0]; w1 = src[1];
            }
            __syncthreads();
            #pragma unroll
            for (int nt = 0; nt < 4; nt++) {
                wmma::fragment<wmma::accumulator, 16, 16, 16, float> acc;
                wmma::fill_fragment(acc, 0.f);
                #pragma unroll
                for (int ks = 0; ks < 4; ks++) {
                    wmma::fragment<wmma::matrix_b, 16, 16, 16, __half, wmma::row_major> b;
                    wmma::load_matrix_sync(b, WB + ks * 16 * WB_LD + nt * 16, WB_LD);
                    wmma::mma_sync(acc, a1[ks], b, acc);
                }
                wmma::store_matrix_sync(YS + wrow * Y1_LD + nt * 16, acc, Y1_LD,
                                        wmma::mem_row_major);
            }
            __syncwarp();   // own-strip YS visible to own warp
            {   // epilogue: node en (own strip), q = nc*2 + qsel, vectorized reads
                float a0 = 0.f, a1s = 0.f, a2 = 0.f;
                const float4* yv4 = (const float4*)(YS + en * Y1_LD + qsel * 32);
                #pragma unroll
                for (int bq = 0; bq < 4; bq++) {
                    float4 ya = yv4[2 * bq], yb = yv4[2 * bq + 1];
                    float yy[8] = {ya.x, ya.y, ya.z, ya.w, yb.x, yb.y, yb.z, yb.w};
                    #pragma unroll
                    for (int t = 0; t < 4; t++) {
                        int v2 = bq * 4 + t;
                        __half2 p0 = *(__half2*)&vc[3 * v2];
                        __half2 p1 = *(__half2*)&vc[3 * v2 + 1];
                        __half2 p2 = *(__half2*)&vc[3 * v2 + 2];
                        float y0 = yy[2 * t], y1 = yy[2 * t + 1];
                        a0  += y0 * __low2float(p0);  a1s += y0 * __high2float(p0); a2 += y0 * __low2float(p1);
                        a0  += y1 * __high2float(p1); a1s += y1 * __low2float(p2);  a2 += y1 * __high2float(p2);
                    }
                }
                int q = nc * 2 + qsel;
                orow[64 + q * 3]     = a0;
                orow[64 + q * 3 + 1] = a1s;
                orow[64 + q * 3 + 2] = a2;
            }
            __syncwarp();   // epilogue reads done before next chunk's YS stores
        }
    }
    __syncthreads();   // GEMM1 done before region C reuse

    // ======== GEMM 2: out2 via symmetric pair features ========
    {
        wmma::fragment<wmma::accumulator, 16, 16, 16, float> acc2[5];
        #pragma unroll
        for (int m = 0; m < 5; m++) wmma::fill_fragment(acc2[m], 0.f);

        const int pi = tid >> 4;      // pair in group (0..15)
        const int mh = tid & 15;      // m-chunk of 8 nodes
        float4 w2;
        if (tid < 160) {
            const float4* src = (const float4*)(d_Wc2 + (size_t)(tid >> 1) * 16 + (tid & 1) * 8);
            w2 = src[0];
        }

        for (int pg = 0; pg < PGRPS; pg++) {
            __half* XT = (__half*)(smem + ((pg & 1) ? C2_XT1 : C2_XT0));
            __half* WB = (__half*)(smem + ((pg & 1) ? C2_WB1 : C2_WB0));
            if (tid < 160) *(float4*)(WB + (tid >> 1) * W2_LD + (tid & 1) * 8) = w2;
            unsigned int pr = d_pairs2[pg * 16 + pi];
            int u = pr >> 8, v = pr & 255;
            H8 ua0 = *(const H8*)(vT + (u * 3 + 0) * LD + mh * 8);
            H8 ua1 = *(const H8*)(vT + (u * 3 + 1) * LD + mh * 8);
            H8 ua2 = *(const H8*)(vT + (u * 3 + 2) * LD + mh * 8);
            H8 vb0 = *(const H8*)(vT + (v * 3 + 0) * LD + mh * 8);
            H8 vb1 = *(const H8*)(vT + (v * 3 + 1) * LD + mh * 8);
            H8 vb2 = *(const H8*)(vT + (v * 3 + 2) * LD + mh * 8);
            H8 r0, r1, r2, r3, r4;
            #pragma unroll
            for (int j = 0; j < 4; j++) {
                __half2 a0 = ua0.h[j], a1 = ua1.h[j], a2 = ua2.h[j];
                __half2 b0 = vb0.h[j], b1 = vb1.h[j], b2 = vb2.h[j];
                __half2 aa = __hmul2(a0, b0);
                __half2 bb = __hmul2(a1, b1);
                __half2 cc = __hmul2(a2, b2);
                r0.h[j] = __hfma2(a0, b1, __hmul2(a1, b0));
                r1.h[j] = __hfma2(a1, b2, __hmul2(a2, b1));
                r2.h[j] = __hsub2(__hsub2(__hadd2(cc, cc), aa), bb);
                r3.h[j] = __hfma2(a0, b2, __hmul2(a2, b0));
                r4.h[j] = __hsub2(aa, bb);
            }
            *(H8*)(XT + (0 * 16 + pi) * LD + mh * 8) = r0;
            *(H8*)(XT + (1 * 16 + pi) * LD + mh * 8) = r1;
            *(H8*)(XT + (2 * 16 + pi) * LD + mh * 8) = r2;
            *(H8*)(XT + (3 * 16 + pi) * LD + mh * 8) = r3;
            *(H8*)(XT + (4 * 16 + pi) * LD + mh * 8) = r4;
            if (pg + 1 < PGRPS && tid < 160) {
                const float4* src = (const float4*)(d_Wc2 + (size_t)(pg + 1) * 80 * 16
                                                    + (size_t)(tid >> 1) * 16 + (tid & 1) * 8);
                w2 = src[0];
            }
            __syncthreads();
            #pragma unroll
            for (int mf = 0; mf < 5; mf++) {
                wmma::fragment<wmma::matrix_a, 16, 16, 16, __half, wmma::col_major> a;
                wmma::fragment<wmma::matrix_b, 16, 16, 16, __half, wmma::row_major> b;
                wmma::load_matrix_sync(a, XT + (mf * 16) * LD + wrow, LD);
                wmma::load_matrix_sync(b, WB + (mf * 16) * W2_LD, W2_LD);
                wmma::mma_sync(acc2[mf], a, b, acc2[mf]);
            }
        }
        __syncthreads();   // all mma done before staging overwrites region C
        float* YS = (float*)(smem + C2_YS);
        #pragma unroll
        for (int m = 0; m < 5; m++)
            wmma::store_matrix_sync(YS + wrow + (m * 16) * YS_LD, acc2[m], YS_LD,
                                    wmma::mem_col_major);
        __syncthreads();
        for (int idx = tid; idx < CTA_M * 80; idx += THREADS) {
            int n = idx / 80, c = idx % 80;
            int m = c >> 4, r = c & 15;
            out[(size_t)(nodeBase + n) * DOUT + 160 + r * 5 + m] = YS[n + c * YS_LD];
        }
    }
}

// ================= launch =================
extern "C" void kernel_launch(void* const* d_in, const int* in_sizes, int n_in,
                              void* d_out, int out_size) {
    const float* feats = (const float*)d_in[0];
    const float* gates = (const float*)d_in[1];
    const float* Wss0  = (const float*)d_in[2];
    const float* Wsv1  = (const float*)d_in[3];
    const float* Wvv0  = (const float*)d_in[4];
    const float* Wvv2  = (const float*)d_in[5];
    float* out = (float*)d_out;

    static bool attr_set = false;
    if (!attr_set) {
        cudaFuncSetAttribute(nltsq_main, cudaFuncAttributeMaxDynamicSharedMemorySize, SMEM_TOTAL);
        attr_set = true;
    }

    prep_all<<<(N_ALL + 255) / 256, 256>>>(gates, Wss0, Wsv1, Wvv0, Wvv2);
    nltsq_main<<<NODES / CTA_M, THREADS, SMEM_TOTAL>>>(feats, out);
}

// round 10
// speedup vs baseline: 8.9571x; 1.1356x over previous
#include <cuda_runtime.h>
#include <cuda_fp16.h>
#include <mma.h>
#include <math.h>
#include <stdint.h>

using namespace nvcuda;

// ================= problem constants =================
#define NODES   32768
#define CTA_M   128
#define THREADS 256
#define DOUT    240
#define KTOT    2624            // 2080 ss + 528 vv + 16 pad = 41*64
#define KCH0    41
#define NPAIR2  528
#define PGRPS   33              // 528/16

// ================= smem layout =================
#define LD       136            // halves
#define WB_LD    72             // halves
#define W2_LD    24             // halves
#define YS_LD    132            // floats (GEMM2 col-major staging)
#define Y1_LD    68             // floats (GEMM1 row-major staging)

#define OFF_ST   0              // sT[64][136]  half  17408
#define OFF_VT   17408          // vT[96][136]  half  26112
#define OFF_C    43520          // union region       53248
#define SMEM_TOTAL 96768

// region C sub-layouts (phase-exclusive)
#define C_XT0   (OFF_C)             // GEMM0 X tile buf0   17408
#define C_XT1   (OFF_C + 17408)     //              buf1   17408
#define C_WB0   (OFF_C + 34816)     // GEMM0 W tile buf0    9216
#define C_WB1   (OFF_C + 44032)     //              buf1    9216
#define C1_WB0  (OFF_C)             // GEMM1 W buf0         9216
#define C1_WB1  (OFF_C + 9216)      //         buf1         9216
#define C1_YS   (OFF_C + 18432)     // GEMM1 staging (row-major 128x68 f) 34816
#define C2_XT0  (OFF_C)             // GEMM2 feat buf0     21760
#define C2_XT1  (OFF_C + 21760)     //            buf1     21760
#define C2_WB0  (OFF_C + 43520)     // GEMM2 W buf0         3840
#define C2_WB1  (OFF_C + 47360)     //          buf1        3840
#define C2_YS   (OFF_C)             // GEMM2 staging (post-loop) 42240

struct alignas(16) H8 { __half2 h[4]; };

// ================= preprocessed weights (gmem) =================
__device__ __half d_Wcat[KTOT * 64];        // [k][p]
__device__ __half d_Wc1 [64 * 1024];        // [u][q*32+v]
__device__ __half d_Wc2 [PGRPS * 80 * 16];  // [(pg*80 + m*16 + pi)][r]
__device__ unsigned short d_pairs [KTOT];
__device__ unsigned short d_pairs2[NPAIR2];
__device__ float d_g[32];

#define N_CAT (KTOT * 64)
#define B_C1  N_CAT
#define N_C1  (64 * 1024)
#define B_C2  (B_C1 + N_C1)
#define N_C2  (PGRPS * 80 * 16)
#define B_PR  (B_C2 + N_C2)
#define B_PR2 (B_PR + KTOT)
#define B_G   (B_PR2 + NPAIR2)
#define N_ALL (B_G + 32)

// ================= prep kernel =================
__device__ __forceinline__ void pair_decode(int k, int width, int& u, int& v) {
    int uu = 0, rem = k;
    while (rem >= width - uu) { rem -= width - uu; uu++; }
    u = uu; v = uu + rem;
}

__global__ void prep_all(const float* __restrict__ gates, const float* __restrict__ Wss0,
                         const float* __restrict__ Wsv1, const float* __restrict__ Wvv0,
                         const float* __restrict__ Wvv2) {
    int idx = blockIdx.x * blockDim.x + threadIdx.x;
    if (idx >= N_ALL) return;
    const float c0  = rsqrtf(5120.f);
    const float cvv = c0 * rsqrtf(3.f);
    const float c1  = rsqrtf(2048.f);
    const float c2  = 0.03125f;
    const float is2 = 0.70710678118654752f;
    const float is6 = 0.40824829046386302f;

    if (idx < N_CAT) {
        int k = idx >> 6, p = idx & 63;
        float val = 0.f;
        if (k < 2080) {
            int u, v; pair_decode(k, 64, u, v);
            val = c0 * Wss0[(u * 64 + v) * 64 + p];
            if (u != v) val += c0 * Wss0[(v * 64 + u) * 64 + p];
        } else if (k < 2608) {
            int u, v; pair_decode(k - 2080, 32, u, v);
            val = cvv * Wvv0[(u * 32 + v) * 64 + p];
            if (u != v) val += cvv * Wvv0[(v * 32 + u) * 64 + p];
        }
        d_Wcat[idx] = __float2half_rn(val);
    } else if (idx < B_C2) {
        int o = idx - B_C1;
        int u = o >> 10, n = o & 1023;
        int q = n >> 5, v = n & 31;
        d_Wc1[o] = __float2half_rn(c1 * Wsv1[u * 1024 + v * 32 + q]);
    } else if (idx < B_PR) {
        int o = idx - B_C2;
        int k2 = o >> 4, r = o & 15;
        int pg = k2 / 80, rem = k2 % 80;
        int m = rem >> 4, pi = rem & 15;
        int pair = pg * 16 + pi;
        int u, v; pair_decode(pair, 32, u, v);
        float w = Wvv2[(u * 32 + v) * 16 + r];
        if (u != v) w += Wvv2[(v * 32 + u) * 16 + r];
        float sc = (m == 2) ? is6 : is2;
        d_Wc2[o] = __float2half_rn(c2 * sc * w);
    } else if (idx < B_PR2) {
        int k = idx - B_PR;
        unsigned short pr = 0xFFFF;
        if (k < 2080)      { int u, v; pair_decode(k, 64, u, v);        pr = (unsigned short)((u << 8) | v); }
        else if (k < 2608) { int u, v; pair_decode(k - 2080, 32, u, v); pr = (unsigned short)((u << 8) | v); }
        d_pairs[k] = pr;
    } else if (idx < B_G) {
        int k = idx - B_PR2;
        int u, v; pair_decode(k, 32, u, v);
        d_pairs2[k] = (unsigned short)((u << 8) | v);
    } else {
        int i = idx - B_G;
        d_g[i] = tanhf(gates[i]);
    }
}

// ================= main kernel =================
__global__ __launch_bounds__(THREADS, 2) void nltsq_main(
    const float* __restrict__ feats, float* __restrict__ out) {
    extern __shared__ char smem[];
    __half* sT = (__half*)(smem + OFF_ST);
    __half* vT = (__half*)(smem + OFF_VT);

    const int tid  = threadIdx.x;
    const int wid  = tid >> 5;
    const int lane = tid & 31;
    const int wrow = wid * 16;
    const int nodeBase = blockIdx.x * CTA_M;

    // ---- Phase A: load + activate (vectorized gmem reads, transposed fp16 stores) ----
    for (int idx = tid; idx < CTA_M * 40; idx += THREADS) {
        int n = idx / 40, c4 = idx % 40;
        float4 f = ((const float4*)(feats + (size_t)(nodeBase + n) * 160))[c4];
        int c = c4 * 4;
        if (c < 64) {
            sT[(c + 0) * LD + n] = __float2half_rn(tanhf(f.x));
            sT[(c + 1) * LD + n] = __float2half_rn(tanhf(f.y));
            sT[(c + 2) * LD + n] = __float2half_rn(tanhf(f.z));
            sT[(c + 3) * LD + n] = __float2half_rn(tanhf(f.w));
        } else {
            int j = c - 64;
            vT[(j + 0) * LD + n] = __float2half_rn(f.x * d_g[(j + 0) / 3]);
            vT[(j + 1) * LD + n] = __float2half_rn(f.y * d_g[(j + 1) / 3]);
            vT[(j + 2) * LD + n] = __float2half_rn(f.z * d_g[(j + 2) / 3]);
            vT[(j + 3) * LD + n] = __float2half_rn(f.w * d_g[(j + 3) / 3]);
        }
    }

    const int k4  = tid >> 2;   // 0..63 (WB store mapping)
    const int qtr = tid & 3;
    const int kr8 = tid >> 3;   // 0..31 (build mapping: k-row)
    const int m8  = tid & 7;    //        m-oct (16B granularity, conflict-free)

    float4 w0, w1;
    {   // prefetch Wcat chunk 0
        const float4* src = (const float4*)(d_Wcat + (size_t)k4 * 64 + qtr * 16);
        w0 = src[0]; w1 = src[1];
    }
    __syncthreads();

    // ======== GEMM 0: out0[128x64] = X[128x2624] @ Wcat (single-sync pipeline) ========
    {
        // warp tile: (M32, N32). wm = wid>>1 (0..3), wn = wid&1 (0..1)
        const int mrow = (wid >> 1) * 32;
        const int ncol = (wid & 1) * 32;
        wmma::fragment<wmma::accumulator, 16, 16, 16, float> acc[2][2];
        #pragma unroll
        for (int i = 0; i < 2; i++)
            #pragma unroll
            for (int j = 0; j < 2; j++) wmma::fill_fragment(acc[i][j], 0.f);

        for (int kc = 0; kc < KCH0; kc++) {
            __half* XT = (__half*)(smem + ((kc & 1) ? C_XT1 : C_XT0));
            __half* WB = (__half*)(smem + ((kc & 1) ? C_WB1 : C_WB0));
            {   // store prefetched W chunk
                float4* dst = (float4*)(WB + k4 * WB_LD + qtr * 16);
                dst[0] = w0; dst[1] = w1;
            }
            // build X: thread handles k-rows kr8, kr8+32; 16 halves each at m8*8, m8*8+64.
            // bank-conflict-free: per 8-lane phase, one row, 8 distinct 16B chunks.
            #pragma unroll
            for (int pass = 0; pass < 2; pass++) {
                int kr = kr8 + pass * 32;
                int kglob = kc * 64 + kr;
                unsigned int pr = d_pairs[kglob];
                int u = pr >> 8, v = pr & 255;
                __half* xbase = XT + kr * LD + m8 * 8;
                if (kglob < 2080) {
                    const __half* su = sT + u * LD + m8 * 8;
                    const __half* sv = sT + v * LD + m8 * 8;
                    #pragma unroll
                    for (int h = 0; h < 2; h++) {
                        H8 a = *(const H8*)(su + h * 64);
                        H8 b = *(const H8*)(sv + h * 64);
                        H8 r;
                        #pragma unroll
                        for (int j = 0; j < 4; j++) r.h[j] = __hmul2(a.h[j], b.h[j]);
                        *(H8*)(xbase + h * 64) = r;
                    }
                } else if (kglob < 2608) {
                    const __half* au = vT + u * 3 * LD + m8 * 8;
                    const __half* bv = vT + v * 3 * LD + m8 * 8;
                    #pragma unroll
                    for (int h = 0; h < 2; h++) {
                        H8 x0 = *(const H8*)(au + 0 * LD + h * 64);
                        H8 x1 = *(const H8*)(au + 1 * LD + h * 64);
                        H8 x2 = *(const H8*)(au + 2 * LD + h * 64);
                        H8 y0 = *(const H8*)(bv + 0 * LD + h * 64);
                        H8 y1 = *(const H8*)(bv + 1 * LD + h * 64);
                        H8 y2 = *(const H8*)(bv + 2 * LD + h * 64);
                        H8 r;
                        #pragma unroll
                        for (int j = 0; j < 4; j++)
                            r.h[j] = __hfma2(x0.h[j], y0.h[j],
                                     __hfma2(x1.h[j], y1.h[j], __hmul2(x2.h[j], y2.h[j])));
                        *(H8*)(xbase + h * 64) = r;
                    }
                } else {
                    H8 z;
                    #pragma unroll
                    for (int j = 0; j < 4; j++) z.h[j] = __half2half2(__half(0.f));
                    *(H8*)(xbase) = z;
                    *(H8*)(xbase + 64) = z;
                }
            }
            if (kc + 1 < KCH0) {   // prefetch next W chunk
                const float4* src = (const float4*)(d_Wcat + (size_t)(kc + 1) * 64 * 64
                                                    + (size_t)k4 * 64 + qtr * 16);
                w0 = src[0]; w1 = src[1];
            }
            __syncthreads();        // tiles ready -> mma; WAR covered by next iter's sync
            #pragma unroll
            for (int ks = 0; ks < 4; ks++) {
                wmma::fragment<wmma::matrix_a, 16, 16, 16, __half, wmma::col_major> a[2];
                wmma::fragment<wmma::matrix_b, 16, 16, 16, __half, wmma::row_major> b[2];
                #pragma unroll
                for (int i = 0; i < 2; i++)
                    wmma::load_matrix_sync(a[i], XT + ks * 16 * LD + mrow + i * 16, LD);
                #pragma unroll
                for (int j = 0; j < 2; j++)
                    wmma::load_matrix_sync(b[j], WB + ks * 16 * WB_LD + ncol + j * 16, WB_LD);
                #pragma unroll
                for (int i = 0; i < 2; i++)
                    #pragma unroll
                    for (int j = 0; j < 2; j++)
                        wmma::mma_sync(acc[i][j], a[i], b[j], acc[i][j]);
            }
        }
        #pragma unroll
        for (int i = 0; i < 2; i++)
            #pragma unroll
            for (int j = 0; j < 2; j++)
                wmma::store_matrix_sync(out + (size_t)(nodeBase + mrow + i * 16) * DOUT
                                        + ncol + j * 16, acc[i][j], DOUT, wmma::mem_row_major);
    }

    // ---- cache own-strip node's v-column (node en) as 48 half2 ----
    const int en   = wrow + (lane & 15);    // node within OWN warp's strip
    const int qsel = lane >> 4;
    uint32_t vc[48];
    #pragma unroll
    for (int r = 0; r < 48; r++) {
        __half lo = vT[(2 * r) * LD + en];
        __half hi = vT[(2 * r + 1) * LD + en];
        vc[r] = (uint32_t)__half_as_ushort(lo) | ((uint32_t)__half_as_ushort(hi) << 16);
    }
    float* orow = out + (size_t)(nodeBase + en) * DOUT;

    {   // prefetch Wc1 chunk 0
        const float4* src = (const float4*)(d_Wc1 + (size_t)k4 * 1024 + qtr * 16);
        w0 = src[0]; w1 = src[1];
    }
    __syncthreads();   // GEMM0 mma fully done before region C reuse

    // ======== GEMM 1: Y = sH @ Wc1 (16 chunks of 64 cols); out1 = Y . v ========
    {
        wmma::fragment<wmma::matrix_a, 16, 16, 16, __half, wmma::col_major> a1[4];
        #pragma unroll
        for (int ks = 0; ks < 4; ks++)
            wmma::load_matrix_sync(a1[ks], sT + ks * 16 * LD + wrow, LD);
        float* YS = (float*)(smem + C1_YS);     // row-major [128][Y1_LD]

        for (int nc = 0; nc < 16; nc++) {
            __half* WB = (__half*)(smem + ((nc & 1) ? C1_WB1 : C1_WB0));
            {
                float4* dst = (float4*)(WB + k4 * WB_LD + qtr * 16);
                dst[0] = w0; dst[1] = w1;
            }
            if (nc + 1 < 16) {
                const float4* src = (const float4*)(d_Wc1 + (size_t)k4 * 1024
                                                    + (nc + 1) * 64 + qtr * 16);
                w0 = src[0]; w1 = src[1];
            }
            __syncthreads();
            #pragma unroll
            for (int nt = 0; nt < 4; nt++) {
                wmma::fragment<wmma::accumulator, 16, 16, 16, float> acc;
                wmma::fill_fragment(acc, 0.f);
                #pragma unroll
                for (int ks = 0; ks < 4; ks++) {
                    wmma::fragment<wmma::matrix_b, 16, 16, 16, __half, wmma::row_major> b;
                    wmma::load_matrix_sync(b, WB + ks * 16 * WB_LD + nt * 16, WB_LD);
                    wmma::mma_sync(acc, a1[ks], b, acc);
                }
                wmma::store_matrix_sync(YS + wrow * Y1_LD + nt * 16, acc, Y1_LD,
                                        wmma::mem_row_major);
            }
            __syncwarp();   // own-strip YS visible to own warp
            {   // epilogue: node en (own strip), q = nc*2 + qsel, vectorized reads
                float a0 = 0.f, a1s = 0.f, a2 = 0.f;
                const float4* yv4 = (const float4*)(YS + en * Y1_LD + qsel * 32);
                #pragma unroll
                for (int bq = 0; bq < 4; bq++) {
                    float4 ya = yv4[2 * bq], yb = yv4[2 * bq + 1];
                    float yy[8] = {ya.x, ya.y, ya.z, ya.w, yb.x, yb.y, yb.z, yb.w};
                    #pragma unroll
                    for (int t = 0; t < 4; t++) {
                        int v2 = bq * 4 + t;
                        __half2 p0 = *(__half2*)&vc[3 * v2];
                        __half2 p1 = *(__half2*)&vc[3 * v2 + 1];
                        __half2 p2 = *(__half2*)&vc[3 * v2 + 2];
                        float y0 = yy[2 * t], y1 = yy[2 * t + 1];
                        a0  += y0 * __low2float(p0);  a1s += y0 * __high2float(p0); a2 += y0 * __low2float(p1);
                        a0  += y1 * __high2float(p1); a1s += y1 * __low2float(p2);  a2 += y1 * __high2float(p2);
                    }
                }
                int q = nc * 2 + qsel;
                orow[64 + q * 3]     = a0;
                orow[64 + q * 3 + 1] = a1s;
                orow[64 + q * 3 + 2] = a2;
            }
            __syncwarp();   // epilogue reads done before next chunk's YS stores
        }
    }
    __syncthreads();   // GEMM1 done before region C reuse

    // ======== GEMM 2: out2 via symmetric pair features ========
    {
        wmma::fragment<wmma::accumulator, 16, 16, 16, float> acc2[5];
        #pragma unroll
        for (int m = 0; m < 5; m++) wmma::fill_fragment(acc2[m], 0.f);

        const int pi = tid >> 4;      // pair in group (0..15)
        const int mh = tid & 15;      // m-chunk of 8 nodes
        float4 w2;
        if (tid < 160) {
            const float4* src = (const float4*)(d_Wc2 + (size_t)(tid >> 1) * 16 + (tid & 1) * 8);
            w2 = src[0];
        }

        for (int pg = 0; pg < PGRPS; pg++) {
            __half* XT = (__half*)(smem + ((pg & 1) ? C2_XT1 : C2_XT0));
            __half* WB = (__half*)(smem + ((pg & 1) ? C2_WB1 : C2_WB0));
            if (tid < 160) *(float4*)(WB + (tid >> 1) * W2_LD + (tid & 1) * 8) = w2;
            unsigned int pr = d_pairs2[pg * 16 + pi];
            int u = pr >> 8, v = pr & 255;
            H8 ua0 = *(const H8*)(vT + (u * 3 + 0) * LD + mh * 8);
            H8 ua1 = *(const H8*)(vT + (u * 3 + 1) * LD + mh * 8);
            H8 ua2 = *(const H8*)(vT + (u * 3 + 2) * LD + mh * 8);
            H8 vb0 = *(const H8*)(vT + (v * 3 + 0) * LD + mh * 8);
            H8 vb1 = *(const H8*)(vT + (v * 3 + 1) * LD + mh * 8);
            H8 vb2 = *(const H8*)(vT + (v * 3 + 2) * LD + mh * 8);
            H8 r0, r1, r2, r3, r4;
            #pragma unroll
            for (int j = 0; j < 4; j++) {
                __half2 a0 = ua0.h[j], a1 = ua1.h[j], a2 = ua2.h[j];
                __half2 b0 = vb0.h[j], b1 = vb1.h[j], b2 = vb2.h[j];
                __half2 aa = __hmul2(a0, b0);
                __half2 bb = __hmul2(a1, b1);
                __half2 cc = __hmul2(a2, b2);
                r0.h[j] = __hfma2(a0, b1, __hmul2(a1, b0));
                r1.h[j] = __hfma2(a1, b2, __hmul2(a2, b1));
                r2.h[j] = __hsub2(__hsub2(__hadd2(cc, cc), aa), bb);
                r3.h[j] = __hfma2(a0, b2, __hmul2(a2, b0));
                r4.h[j] = __hsub2(aa, bb);
            }
            *(H8*)(XT + (0 * 16 + pi) * LD + mh * 8) = r0;
            *(H8*)(XT + (1 * 16 + pi) * LD + mh * 8) = r1;
            *(H8*)(XT + (2 * 16 + pi) * LD + mh * 8) = r2;
            *(H8*)(XT + (3 * 16 + pi) * LD + mh * 8) = r3;
            *(H8*)(XT + (4 * 16 + pi) * LD + mh * 8) = r4;
            if (pg + 1 < PGRPS && tid < 160) {
                const float4* src = (const float4*)(d_Wc2 + (size_t)(pg + 1) * 80 * 16
                                                    + (size_t)(tid >> 1) * 16 + (tid & 1) * 8);
                w2 = src[0];
            }
            __syncthreads();
            #pragma unroll
            for (int mf = 0; mf < 5; mf++) {
                wmma::fragment<wmma::matrix_a, 16, 16, 16, __half, wmma::col_major> a;
                wmma::fragment<wmma::matrix_b, 16, 16, 16, __half, wmma::row_major> b;
                wmma::load_matrix_sync(a, XT + (mf * 16) * LD + wrow, LD);
                wmma::load_matrix_sync(b, WB + (mf * 16) * W2_LD, W2_LD);
                wmma::mma_sync(acc2[mf], a, b, acc2[mf]);
            }
        }
        __syncthreads();   // all mma done before staging overwrites region C
        float* YS = (float*)(smem + C2_YS);
        #pragma unroll
        for (int m = 0; m < 5; m++)
            wmma::store_matrix_sync(YS + wrow + (m * 16) * YS_LD, acc2[m], YS_LD,
                                    wmma::mem_col_major);
        __syncthreads();
        for (int idx = tid; idx < CTA_M * 80; idx += THREADS) {
            int n = idx / 80, c = idx % 80;
            int m = c >> 4, r = c & 15;
            out[(size_t)(nodeBase + n) * DOUT + 160 + r * 5 + m] = YS[n + c * YS_LD];
        }
    }
}

// ================= launch =================
extern "C" void kernel_launch(void* const* d_in, const int* in_sizes, int n_in,
                              void* d_out, int out_size) {
    const float* feats = (const float*)d_in[0];
    const float* gates = (const float*)d_in[1];
    const float* Wss0  = (const float*)d_in[2];
    const float* Wsv1  = (const float*)d_in[3];
    const float* Wvv0  = (const float*)d_in[4];
    const float* Wvv2  = (const float*)d_in[5];
    float* out = (float*)d_out;

    static bool attr_set = false;
    if (!attr_set) {
        cudaFuncSetAttribute(nltsq_main, cudaFuncAttributeMaxDynamicSharedMemorySize, SMEM_TOTAL);
        attr_set = true;
    }

    prep_all<<<(N_ALL + 255) / 256, 256>>>(gates, Wss0, Wsv1, Wvv0, Wvv2);
    nltsq_main<<<NODES / CTA_M, THREADS, SMEM_TOTAL>>>(feats, out);
}